// round 8
// baseline (speedup 1.0000x reference)
#include <cuda_runtime.h>
#include <cstdint>

#define N_NODES 50000
#define N_EDGES 800000
#define D 128
#define VOCAB 30000
#define BATCH 1024
#define CTX_LEN 50

// ---------------- scratch (no allocations allowed) ----------------
__device__ float g_z[(size_t)N_NODES * D];
__device__ float g_h[(size_t)N_NODES * D];
__device__ float g_in256[BATCH * 256];
__device__ float g_qin[BATCH * 256];
__device__ float g_q1[BATCH * 256];
__device__ float g_stats[512];           // 2 layers x (sum[128], sumsq[128])
__device__ int   g_deg[N_NODES];
__device__ int   g_offs[N_NODES + 1];
__device__ int   g_cursor[N_NODES];
__device__ int2  g_epack[N_EDGES];       // {col, bitcast(norm)}

// ---------------- prep: zero degree counters + BN stats banks ----------------
__global__ void prep_kernel(int* __restrict__ deg, float* __restrict__ stats) {
    int i = blockIdx.x * blockDim.x + threadIdx.x;
    if (i < N_NODES) deg[i] = 0;
    if (i < 512) stats[i] = 0.f;
}

// ---------------- histogram of edge rows ----------------
__global__ void hist_kernel(const int* __restrict__ rows, int* __restrict__ deg) {
    int e = blockIdx.x * blockDim.x + threadIdx.x;
    if (e < N_EDGES) atomicAdd(&deg[rows[e]], 1);
}

// ---------------- exclusive scan of deg -> offs, cursor (single block) ----------------
__device__ __forceinline__ int warp_incl_scan(int v, int lane) {
#pragma unroll
    for (int o = 1; o < 32; o <<= 1) {
        int t = __shfl_up_sync(0xffffffffu, v, o);
        if (lane >= o) v += t;
    }
    return v;
}

__global__ void scan_kernel(const int* __restrict__ deg, int* __restrict__ offs,
                            int* __restrict__ cursor) {
    __shared__ int s_w[32];
    __shared__ int s_ws[32];
    __shared__ int s_carry;
    int tid = threadIdx.x;               // 1024 threads
    int lane = tid & 31, wid = tid >> 5;
    if (tid == 0) s_carry = 0;
    __syncthreads();
    for (int base = 0; base < N_NODES; base += 1024) {
        int i = base + tid;
        int v = (i < N_NODES) ? deg[i] : 0;
        int ws = warp_incl_scan(v, lane);
        if (lane == 31) s_w[wid] = ws;
        __syncthreads();
        if (wid == 0) {
            int t = s_w[lane];
            t = warp_incl_scan(t, lane);
            s_ws[lane] = t;
        }
        __syncthreads();
        int incl = ws + (wid ? s_ws[wid - 1] : 0);
        int excl = s_carry + incl - v;
        if (i < N_NODES) { offs[i] = excl; cursor[i] = excl; }
        __syncthreads();
        if (tid == 0) s_carry += s_ws[31];
        __syncthreads();
    }
    if (tid == 0) offs[N_NODES] = s_carry;   // == N_EDGES
}

// ---------------- counting-sort permute: packed (col, norm) grouped by row ----------
__global__ void permute_kernel(const int* __restrict__ rows, const int* __restrict__ cols,
                               const float* __restrict__ norm, int* __restrict__ cursor,
                               int2* __restrict__ ep) {
    int e = blockIdx.x * blockDim.x + threadIdx.x;
    if (e >= N_EDGES) return;
    int r = rows[e];
    int pos = atomicAdd(&cursor[r], 1);
    ep[pos] = make_int2(cols[e], __float_as_int(norm[e]));
}

// ========== fused GCN layer core: z = relu((A @ h) @ W^T), stats += (sum, sumsq) =====
// Block = 256 threads = 8 warps, 64 nodes. Warp w gathers its own microtile rows
// (w*8 .. w*8+7) straight into sA, then the FFMA mainloop consumes sA/sB.
#define SBK 129
#define GEMM_SMEM ((64 * 128 + 128 * SBK) * 4)

__global__ void __launch_bounds__(256, 2)
gcn_fused_kernel(const int* __restrict__ offs, const int2* __restrict__ ep,
                 const float* __restrict__ h, const float* __restrict__ W,
                 float* __restrict__ z, float* __restrict__ stats) {
    extern __shared__ float sm[];
    float* sA = sm;              // [64][128]  gathered agg tile
    float* sB = sm + 64 * 128;   // [128][SBK] weight tile
    int tid = threadIdx.x;
    int lane = tid & 31, wid = tid >> 5;
    int bm = blockIdx.x * 64;

    // W tile: [n][k] natural layout, stride 129
    for (int i = tid; i < 128 * 32; i += 256) {
        int n = i >> 5, k4 = i & 31;
        float4 v = *(const float4*)(W + (size_t)n * D + k4 * 4);
        float* p = sB + n * SBK + k4 * 4;
        p[0] = v.x; p[1] = v.y; p[2] = v.z; p[3] = v.w;
    }

    // stage the 9 CSR boundaries this warp needs (nodes bm+wid*8 .. bm+wid*8+8)
    int base_node = bm + wid * 8;
    int boff = 0;
    if (lane < 9) {
        int nd = base_node + lane;
        boff = (nd <= N_NODES) ? offs[nd < N_NODES ? nd : N_NODES] : 0;
    }

    // gather phase: warp wid produces sA rows wid*8 .. wid*8+7
#pragma unroll 1
    for (int i = 0; i < 8; i++) {
        int node = base_node + i;
        float4 a0 = make_float4(0.f, 0.f, 0.f, 0.f);
        float4 a1 = make_float4(0.f, 0.f, 0.f, 0.f);
        float4 a2 = make_float4(0.f, 0.f, 0.f, 0.f);
        float4 a3 = make_float4(0.f, 0.f, 0.f, 0.f);
        if (node < N_NODES) {
            int e   = __shfl_sync(0xffffffffu, boff, i);
            int end = __shfl_sync(0xffffffffu, boff, i + 1);
            for (; e + 3 < end; e += 4) {
                int2 p0 = ep[e],     p1 = ep[e + 1];
                int2 p2 = ep[e + 2], p3 = ep[e + 3];
                float w0 = __int_as_float(p0.y), w1 = __int_as_float(p1.y);
                float w2 = __int_as_float(p2.y), w3 = __int_as_float(p3.y);
                float4 v0 = *((const float4*)(h + (size_t)p0.x * D) + lane);
                float4 v1 = *((const float4*)(h + (size_t)p1.x * D) + lane);
                float4 v2 = *((const float4*)(h + (size_t)p2.x * D) + lane);
                float4 v3 = *((const float4*)(h + (size_t)p3.x * D) + lane);
                a0.x = fmaf(w0, v0.x, a0.x); a0.y = fmaf(w0, v0.y, a0.y);
                a0.z = fmaf(w0, v0.z, a0.z); a0.w = fmaf(w0, v0.w, a0.w);
                a1.x = fmaf(w1, v1.x, a1.x); a1.y = fmaf(w1, v1.y, a1.y);
                a1.z = fmaf(w1, v1.z, a1.z); a1.w = fmaf(w1, v1.w, a1.w);
                a2.x = fmaf(w2, v2.x, a2.x); a2.y = fmaf(w2, v2.y, a2.y);
                a2.z = fmaf(w2, v2.z, a2.z); a2.w = fmaf(w2, v2.w, a2.w);
                a3.x = fmaf(w3, v3.x, a3.x); a3.y = fmaf(w3, v3.y, a3.y);
                a3.z = fmaf(w3, v3.z, a3.z); a3.w = fmaf(w3, v3.w, a3.w);
            }
            for (; e < end; e++) {
                int2 p0 = ep[e];
                float w0 = __int_as_float(p0.y);
                float4 v0 = *((const float4*)(h + (size_t)p0.x * D) + lane);
                a0.x = fmaf(w0, v0.x, a0.x); a0.y = fmaf(w0, v0.y, a0.y);
                a0.z = fmaf(w0, v0.z, a0.z); a0.w = fmaf(w0, v0.w, a0.w);
            }
        }
        a0.x += a1.x; a0.y += a1.y; a0.z += a1.z; a0.w += a1.w;
        a2.x += a3.x; a2.y += a3.y; a2.z += a3.z; a2.w += a3.w;
        a0.x += a2.x; a0.y += a2.y; a0.z += a2.z; a0.w += a2.w;
        *(float4*)(sA + (wid * 8 + i) * 128 + lane * 4) = a0;
    }
    __syncthreads();

    // FFMA mainloop: warp wid computes rows rg..rg+7, cols lane + 32c
    int rg = wid * 8;
    float acc[8][4];
#pragma unroll
    for (int i = 0; i < 8; i++)
#pragma unroll
        for (int c = 0; c < 4; c++) acc[i][c] = 0.f;
#pragma unroll 4
    for (int k = 0; k < 128; k++) {
        float b0 = sB[(lane)      * SBK + k];
        float b1 = sB[(lane + 32) * SBK + k];
        float b2 = sB[(lane + 64) * SBK + k];
        float b3 = sB[(lane + 96) * SBK + k];
#pragma unroll
        for (int i = 0; i < 8; i++) {
            float a = sA[(rg + i) * 128 + k];
            acc[i][0] = fmaf(a, b0, acc[i][0]);
            acc[i][1] = fmaf(a, b1, acc[i][1]);
            acc[i][2] = fmaf(a, b2, acc[i][2]);
            acc[i][3] = fmaf(a, b3, acc[i][3]);
        }
    }

    // epilogue: relu, store z, accumulate BN stats
    float psum[4] = {0.f, 0.f, 0.f, 0.f}, psq[4] = {0.f, 0.f, 0.f, 0.f};
#pragma unroll
    for (int i = 0; i < 8; i++) {
        int gr = bm + rg + i;
        if (gr < N_NODES) {
#pragma unroll
            for (int c = 0; c < 4; c++) {
                float v = fmaxf(acc[i][c], 0.f);
                z[(size_t)gr * D + lane + 32 * c] = v;
                psum[c] += v;
                psq[c] += v * v;
            }
        }
    }
    __syncthreads();
    float* s_sum = sm;
    float* s_sq = sm + 128;
    if (tid < 128) { s_sum[tid] = 0.f; s_sq[tid] = 0.f; }
    __syncthreads();
#pragma unroll
    for (int c = 0; c < 4; c++) {
        atomicAdd(&s_sum[lane + 32 * c], psum[c]);
        atomicAdd(&s_sq[lane + 32 * c], psq[c]);
    }
    __syncthreads();
    if (tid < 128) {
        atomicAdd(&stats[tid], s_sum[tid]);
        atomicAdd(&stats[128 + tid], s_sq[tid]);
    }
}

// ---------------- generic GEMM (batch MLP): out = act(A @ W^T + bias) ----------------
__global__ void __launch_bounds__(256, 2)
gemm_kernel(const float* __restrict__ A, const float* __restrict__ W,
            const float* __restrict__ bias, float* __restrict__ out,
            int M, int N, int K, int ldout, int do_relu) {
    extern __shared__ float sm[];
    float* sA = sm;
    float* sB = sm + 64 * 128;
    int tid = threadIdx.x;
    int lane = tid & 31, wid = tid >> 5;
    int bm = blockIdx.x * 64;
    int bn = blockIdx.y * 128;

    float acc[8][4];
#pragma unroll
    for (int i = 0; i < 8; i++)
#pragma unroll
        for (int c = 0; c < 4; c++) acc[i][c] = 0.f;

    int rg = wid * 8;
    for (int k0 = 0; k0 < K; k0 += 128) {
        __syncthreads();
        for (int i = tid; i < 64 * 32; i += 256) {
            int r = i >> 5, c4 = i & 31;
            int gr = bm + r;
            float4 v = make_float4(0.f, 0.f, 0.f, 0.f);
            if (gr < M) v = *(const float4*)(A + (size_t)gr * K + k0 + c4 * 4);
            *(float4*)(sA + r * 128 + c4 * 4) = v;
        }
        for (int i = tid; i < 128 * 32; i += 256) {
            int n = i >> 5, k4 = i & 31;
            float4 v = *(const float4*)(W + (size_t)(bn + n) * K + k0 + k4 * 4);
            float* p = sB + n * SBK + k4 * 4;
            p[0] = v.x; p[1] = v.y; p[2] = v.z; p[3] = v.w;
        }
        __syncthreads();
#pragma unroll 4
        for (int k = 0; k < 128; k++) {
            float b0 = sB[(lane)      * SBK + k];
            float b1 = sB[(lane + 32) * SBK + k];
            float b2 = sB[(lane + 64) * SBK + k];
            float b3 = sB[(lane + 96) * SBK + k];
#pragma unroll
            for (int i = 0; i < 8; i++) {
                float a = sA[(rg + i) * 128 + k];
                acc[i][0] = fmaf(a, b0, acc[i][0]);
                acc[i][1] = fmaf(a, b1, acc[i][1]);
                acc[i][2] = fmaf(a, b2, acc[i][2]);
                acc[i][3] = fmaf(a, b3, acc[i][3]);
            }
        }
    }

    float bv[4];
#pragma unroll
    for (int c = 0; c < 4; c++) bv[c] = bias ? bias[bn + lane + 32 * c] : 0.f;
#pragma unroll
    for (int i = 0; i < 8; i++) {
        int gr = bm + rg + i;
        if (gr < M) {
#pragma unroll
            for (int c = 0; c < 4; c++) {
                float v = acc[i][c] + bv[c];
                if (do_relu) v = fmaxf(v, 0.f);
                out[(size_t)gr * ldout + bn + lane + 32 * c] = v;
            }
        }
    }
}

// ---------------- BN stats finalize ----------------
__global__ void finalize_stats(float* stats, const float* __restrict__ gamma,
                               const float* __restrict__ beta, float invN) {
    int j = threadIdx.x;
    float s = stats[j], sq = stats[128 + j];
    float mu = s * invN;
    float var = fmaxf(sq * invN - mu * mu, 0.f);
    float rstd = rsqrtf(var + 1e-5f);
    float sc = rstd * gamma[j];
    stats[j] = sc;
    stats[128 + j] = beta[j] - mu * sc;
}

// ---------------- BN apply + residual ----------------
__global__ void bn_res_kernel(const float4* __restrict__ hin, const float4* __restrict__ z,
                              const float* __restrict__ ss, float4* __restrict__ hout, int n4) {
    int i = blockIdx.x * blockDim.x + threadIdx.x;
    int stride = gridDim.x * blockDim.x;
    for (; i < n4; i += stride) {
        int j4 = i & 31;
        float4 zv = z[i];
        float4 hv = hin[i];
        float4 sc = ((const float4*)ss)[j4];
        float4 sh = ((const float4*)(ss + 128))[j4];
        float4 o;
        o.x = hv.x + zv.x * sc.x + sh.x;
        o.y = hv.y + zv.y * sc.y + sh.y;
        o.z = hv.z + zv.z * sc.z + sh.z;
        o.w = hv.w + zv.w * sc.w + sh.w;
        hout[i] = o;
    }
}

// ---------------- context attention pooling -> qin[b][0:128] ----------------
__global__ void attn_kernel(const int* __restrict__ ctx_ids, const float* __restrict__ emb,
                            const float* __restrict__ attn_w, const float* __restrict__ attn_b,
                            float* __restrict__ qin) {
    __shared__ float s_ctx[CTX_LEN * D];
    __shared__ float s_aw[D];
    __shared__ float s_logit[64];
    __shared__ float s_wt[64];
    int b = blockIdx.x;
    int tid = threadIdx.x;          // 128 threads
    int lane = tid & 31, wid = tid >> 5;
    s_aw[tid] = attn_w[tid];
    for (int i = tid; i < CTX_LEN * D; i += 128) {
        int l = i >> 7, d = i & 127;
        int id = ctx_ids[b * CTX_LEN + l];
        s_ctx[i] = emb[(size_t)id * D + d];
    }
    __syncthreads();
    for (int l = wid; l < CTX_LEN; l += 4) {
        float p = 0.f;
#pragma unroll
        for (int c = 0; c < 4; c++)
            p += s_ctx[l * D + lane + 32 * c] * s_aw[lane + 32 * c];
#pragma unroll
        for (int off = 16; off; off >>= 1) p += __shfl_xor_sync(0xffffffffu, p, off);
        if (lane == 0) s_logit[l] = p + attn_b[0];
    }
    __syncthreads();
    if (wid == 0) {
        float x0 = (lane < CTX_LEN) ? s_logit[lane] : -1e30f;
        float x1 = (lane + 32 < CTX_LEN) ? s_logit[lane + 32] : -1e30f;
        float m = fmaxf(x0, x1);
#pragma unroll
        for (int off = 16; off; off >>= 1) m = fmaxf(m, __shfl_xor_sync(0xffffffffu, m, off));
        float e0 = (lane < CTX_LEN) ? expf(x0 - m) : 0.f;
        float e1 = (lane + 32 < CTX_LEN) ? expf(x1 - m) : 0.f;
        float s = e0 + e1;
#pragma unroll
        for (int off = 16; off; off >>= 1) s += __shfl_xor_sync(0xffffffffu, s, off);
        float inv = 1.f / s;
        if (lane < CTX_LEN) s_wt[lane] = e0 * inv;
        if (lane + 32 < CTX_LEN) s_wt[lane + 32] = e1 * inv;
    }
    __syncthreads();
    float acc = 0.f;
    for (int l = 0; l < CTX_LEN; l++) acc += s_wt[l] * s_ctx[l * D + tid];
    qin[b * 256 + tid] = acc;
}

// ---------------- build fusion input ----------------
__global__ void miss_in_kernel(const int* __restrict__ miss_ids, const int* __restrict__ v2fg,
                               const float* __restrict__ emb, const float* __restrict__ graph,
                               float* __restrict__ in256) {
    int idx = blockIdx.x * blockDim.x + threadIdx.x;
    int b = idx >> 7, d = idx & 127;
    if (b >= BATCH) return;
    int mid = miss_ids[b];
    in256[b * 256 + d] = emb[(size_t)mid * D + d];
    int fg = v2fg[mid];
    in256[b * 256 + 128 + d] = (fg >= 0) ? graph[(size_t)fg * D + d] : 0.f;
}

// ---------------- launch ----------------
extern "C" void kernel_launch(void* const* d_in, const int* in_sizes, int n_in,
                              void* d_out, int out_size) {
    const int*   edge_index = (const int*)d_in[0];
    const float* norm       = (const float*)d_in[1];
    const int*   ctx_ids    = (const int*)d_in[2];
    const int*   miss_ids   = (const int*)d_in[3];
    const int*   v2fg       = (const int*)d_in[4];
    const float* emb_table  = (const float*)d_in[5];
    const float* fg_emb     = (const float*)d_in[6];
    const float* gc_w       = (const float*)d_in[7];
    const float* bn_gamma   = (const float*)d_in[8];
    const float* bn_beta    = (const float*)d_in[9];
    const float* attn_w     = (const float*)d_in[10];
    const float* attn_b     = (const float*)d_in[11];
    const float* fusion_w   = (const float*)d_in[12];
    const float* fusion_b   = (const float*)d_in[13];
    const float* proj1_w    = (const float*)d_in[14];
    const float* proj1_b    = (const float*)d_in[15];
    const float* proj2_w    = (const float*)d_in[16];
    const float* proj2_b    = (const float*)d_in[17];

    float* out   = (float*)d_out;
    float* query = out;                       // [1024,128]
    float* graph = out + (size_t)BATCH * D;   // [50000,128]

    float *z, *h, *in256, *qin, *q1, *stats;
    int *deg, *offs, *cursor;
    int2 *ep;
    cudaGetSymbolAddress((void**)&z,      g_z);
    cudaGetSymbolAddress((void**)&h,      g_h);
    cudaGetSymbolAddress((void**)&in256,  g_in256);
    cudaGetSymbolAddress((void**)&qin,    g_qin);
    cudaGetSymbolAddress((void**)&q1,     g_q1);
    cudaGetSymbolAddress((void**)&stats,  g_stats);
    cudaGetSymbolAddress((void**)&deg,    g_deg);
    cudaGetSymbolAddress((void**)&offs,   g_offs);
    cudaGetSymbolAddress((void**)&cursor, g_cursor);
    cudaGetSymbolAddress((void**)&ep,     g_epack);

    cudaFuncSetAttribute(gcn_fused_kernel, cudaFuncAttributeMaxDynamicSharedMemorySize, GEMM_SMEM);
    cudaFuncSetAttribute(gemm_kernel, cudaFuncAttributeMaxDynamicSharedMemorySize, GEMM_SMEM);

    const int* rows = edge_index;
    const int* cols = edge_index + N_EDGES;
    const int total4 = N_NODES * (D / 4);     // 1.6M float4

    // CSR build (once per call; shared by both layers)
    prep_kernel<<<196, 256>>>(deg, stats);
    hist_kernel<<<3125, 256>>>(rows, deg);
    scan_kernel<<<1, 1024>>>(deg, offs, cursor);
    permute_kernel<<<3125, 256>>>(rows, cols, norm, cursor, ep);

    // batch-side attention (independent of graph path)
    attn_kernel<<<BATCH, 128>>>(ctx_ids, emb_table, attn_w, attn_b, qin);

    // GCN layers: fused gather+GEMM+stats, then finalize + BN/residual
    for (int l = 0; l < 2; l++) {
        const float* hin = (l == 0) ? fg_emb : h;
        float* lstats = stats + l * 256;
        gcn_fused_kernel<<<782, 256, GEMM_SMEM>>>(offs, ep, hin, gc_w + (size_t)l * D * D,
                                                  z, lstats);
        finalize_stats<<<1, 128>>>(lstats, bn_gamma + l * D, bn_beta + l * D, 1.0f / N_NODES);
        float* hout = (l == 0) ? h : graph;
        bn_res_kernel<<<6250, 256>>>((const float4*)hin, (const float4*)z, lstats,
                                     (float4*)hout, total4);
    }

    // fusion + projection MLP
    miss_in_kernel<<<BATCH, 128>>>(miss_ids, v2fg, emb_table, graph, in256);
    gemm_kernel<<<dim3(16, 1), 256, GEMM_SMEM>>>(in256, fusion_w, fusion_b, qin + 128,
                                                 BATCH, 128, 256, 256, 0);
    gemm_kernel<<<dim3(16, 2), 256, GEMM_SMEM>>>(qin, proj1_w, proj1_b, q1,
                                                 BATCH, 256, 256, 256, 1);
    gemm_kernel<<<dim3(16, 1), 256, GEMM_SMEM>>>(q1, proj2_w, proj2_b, query,
                                                 BATCH, 128, 256, 128, 0);
}

// round 10
// speedup vs baseline: 1.0905x; 1.0905x over previous
#include <cuda_runtime.h>
#include <cstdint>

#define N_NODES 50000
#define N_EDGES 800000
#define D 128
#define VOCAB 30000
#define BATCH 1024
#define CTX_LEN 50

// ---------------- scratch (no allocations allowed) ----------------
__device__ float g_agg[(size_t)N_NODES * D];
__device__ float g_z[(size_t)N_NODES * D];
__device__ float g_h[(size_t)N_NODES * D];
__device__ float g_in256[BATCH * 256];
__device__ float g_qin[BATCH * 256];
__device__ float g_q1[BATCH * 256];
__device__ float g_stats[512];           // 2 layers x (sum[128], sumsq[128])
__device__ int   g_deg[N_NODES];
__device__ int   g_offs[N_NODES + 4];
__device__ int   g_cursor[N_NODES];
__device__ int2  g_epack[N_EDGES];       // {col, bitcast(norm)}

// ---------------- histogram of edge rows ----------------
__global__ void hist_kernel(const int* __restrict__ rows, int* __restrict__ deg) {
    int e = blockIdx.x * blockDim.x + threadIdx.x;
    if (e < N_EDGES) atomicAdd(&deg[rows[e]], 1);
}

// ---------------- exclusive scan of deg -> offs, cursor (single block, int4) --------
__device__ __forceinline__ int warp_incl_scan(int v, int lane) {
#pragma unroll
    for (int o = 1; o < 32; o <<= 1) {
        int t = __shfl_up_sync(0xffffffffu, v, o);
        if (lane >= o) v += t;
    }
    return v;
}

#define N4 (N_NODES / 4)                 // 12500 int4 groups (N_NODES % 4 == 0)

__global__ void scan_kernel(const int4* __restrict__ deg4, int* __restrict__ offs,
                            int* __restrict__ cursor) {
    __shared__ int s_w[32];
    __shared__ int s_ws[32];
    __shared__ int s_carry;
    int tid = threadIdx.x;               // 1024 threads; 4 elems/thread/iter
    int lane = tid & 31, wid = tid >> 5;
    if (tid == 0) s_carry = 0;
    __syncthreads();
    for (int base = 0; base < N4; base += 1024) {
        int i4 = base + tid;
        int4 v = make_int4(0, 0, 0, 0);
        if (i4 < N4) v = deg4[i4];
        int tsum = v.x + v.y + v.z + v.w;
        int ws = warp_incl_scan(tsum, lane);
        if (lane == 31) s_w[wid] = ws;
        __syncthreads();
        if (wid == 0) s_ws[lane] = warp_incl_scan(s_w[lane], lane);
        __syncthreads();
        int excl = s_carry + ws - tsum + (wid ? s_ws[wid - 1] : 0);
        if (i4 < N4) {
            int o0 = excl;
            int o1 = o0 + v.x;
            int o2 = o1 + v.y;
            int o3 = o2 + v.z;
            int i = i4 * 4;
            offs[i] = o0; offs[i + 1] = o1; offs[i + 2] = o2; offs[i + 3] = o3;
            cursor[i] = o0; cursor[i + 1] = o1; cursor[i + 2] = o2; cursor[i + 3] = o3;
        }
        __syncthreads();
        if (tid == 0) s_carry += s_ws[31];
        __syncthreads();
    }
    if (tid == 0) offs[N_NODES] = s_carry;   // == N_EDGES
}

// ---------------- counting-sort permute: packed (col, norm) grouped by row ----------
__global__ void permute_kernel(const int* __restrict__ rows, const int* __restrict__ cols,
                               const float* __restrict__ norm, int* __restrict__ cursor,
                               int2* __restrict__ ep) {
    int e = blockIdx.x * blockDim.x + threadIdx.x;
    if (e >= N_EDGES) return;
    int r = rows[e];
    int pos = atomicAdd(&cursor[r], 1);
    ep[pos] = make_int2(cols[e], __float_as_int(norm[e]));
}

// ---------------- CSR gather: agg[i] = sum_e norm_e * h[col_e]  (no atomics) ----------
// warp per node; lane owns one float4 of the 128-wide row; 4-wide edge unroll for MLP.
__global__ void gather_kernel(const int* __restrict__ offs, const int2* __restrict__ ep,
                              const float* __restrict__ h, float* __restrict__ agg) {
    int warp = blockIdx.x * (blockDim.x >> 5) + (threadIdx.x >> 5);
    if (warp >= N_NODES) return;
    int lane = threadIdx.x & 31;
    int e = offs[warp], end = offs[warp + 1];
    float4 a0 = make_float4(0.f, 0.f, 0.f, 0.f);
    float4 a1 = make_float4(0.f, 0.f, 0.f, 0.f);
    float4 a2 = make_float4(0.f, 0.f, 0.f, 0.f);
    float4 a3 = make_float4(0.f, 0.f, 0.f, 0.f);
    for (; e + 3 < end; e += 4) {
        int2 p0 = ep[e],     p1 = ep[e + 1];
        int2 p2 = ep[e + 2], p3 = ep[e + 3];
        float w0 = __int_as_float(p0.y), w1 = __int_as_float(p1.y);
        float w2 = __int_as_float(p2.y), w3 = __int_as_float(p3.y);
        float4 v0 = *((const float4*)(h + (size_t)p0.x * D) + lane);
        float4 v1 = *((const float4*)(h + (size_t)p1.x * D) + lane);
        float4 v2 = *((const float4*)(h + (size_t)p2.x * D) + lane);
        float4 v3 = *((const float4*)(h + (size_t)p3.x * D) + lane);
        a0.x = fmaf(w0, v0.x, a0.x); a0.y = fmaf(w0, v0.y, a0.y);
        a0.z = fmaf(w0, v0.z, a0.z); a0.w = fmaf(w0, v0.w, a0.w);
        a1.x = fmaf(w1, v1.x, a1.x); a1.y = fmaf(w1, v1.y, a1.y);
        a1.z = fmaf(w1, v1.z, a1.z); a1.w = fmaf(w1, v1.w, a1.w);
        a2.x = fmaf(w2, v2.x, a2.x); a2.y = fmaf(w2, v2.y, a2.y);
        a2.z = fmaf(w2, v2.z, a2.z); a2.w = fmaf(w2, v2.w, a2.w);
        a3.x = fmaf(w3, v3.x, a3.x); a3.y = fmaf(w3, v3.y, a3.y);
        a3.z = fmaf(w3, v3.z, a3.z); a3.w = fmaf(w3, v3.w, a3.w);
    }
    for (; e < end; e++) {
        int2 p0 = ep[e];
        float w0 = __int_as_float(p0.y);
        float4 v0 = *((const float4*)(h + (size_t)p0.x * D) + lane);
        a0.x = fmaf(w0, v0.x, a0.x); a0.y = fmaf(w0, v0.y, a0.y);
        a0.z = fmaf(w0, v0.z, a0.z); a0.w = fmaf(w0, v0.w, a0.w);
    }
    a0.x += a1.x; a0.y += a1.y; a0.z += a1.z; a0.w += a1.w;
    a2.x += a3.x; a2.y += a3.y; a2.z += a3.z; a2.w += a3.w;
    a0.x += a2.x; a0.y += a2.y; a0.z += a2.z; a0.w += a2.w;
    *((float4*)(agg + (size_t)warp * D) + lane) = a0;
}

// ---------------- generic GEMM: out[M,N] = act(A[M,K] @ W[N,K]^T + bias) ----------------
#define SBK 129
#define GEMM_SMEM ((64 * 128 + 128 * SBK) * 4)

__global__ void __launch_bounds__(256, 2)
gemm_kernel(const float* __restrict__ A, const float* __restrict__ W,
            const float* __restrict__ bias, float* __restrict__ out,
            int M, int N, int K, int ldout, int do_relu, float* __restrict__ stats) {
    extern __shared__ float sm[];
    float* sA = sm;              // [64][128]
    float* sB = sm + 64 * 128;   // [128][SBK]
    int tid = threadIdx.x;
    int lane = tid & 31, wid = tid >> 5;
    int bm = blockIdx.x * 64;
    int bn = blockIdx.y * 128;

    float acc[8][4];
#pragma unroll
    for (int i = 0; i < 8; i++)
#pragma unroll
        for (int c = 0; c < 4; c++) acc[i][c] = 0.f;

    int rg = wid * 8;
    for (int k0 = 0; k0 < K; k0 += 128) {
        __syncthreads();
        for (int i = tid; i < 64 * 32; i += 256) {
            int r = i >> 5, c4 = i & 31;
            int gr = bm + r;
            float4 v = make_float4(0.f, 0.f, 0.f, 0.f);
            if (gr < M) v = *(const float4*)(A + (size_t)gr * K + k0 + c4 * 4);
            *(float4*)(sA + r * 128 + c4 * 4) = v;
        }
        for (int i = tid; i < 128 * 32; i += 256) {
            int n = i >> 5, k4 = i & 31;
            float4 v = *(const float4*)(W + (size_t)(bn + n) * K + k0 + k4 * 4);
            float* p = sB + n * SBK + k4 * 4;
            p[0] = v.x; p[1] = v.y; p[2] = v.z; p[3] = v.w;
        }
        __syncthreads();
#pragma unroll 4
        for (int k = 0; k < 128; k++) {
            float b0 = sB[(lane)      * SBK + k];
            float b1 = sB[(lane + 32) * SBK + k];
            float b2 = sB[(lane + 64) * SBK + k];
            float b3 = sB[(lane + 96) * SBK + k];
#pragma unroll
            for (int i = 0; i < 8; i++) {
                float a = sA[(rg + i) * 128 + k];
                acc[i][0] = fmaf(a, b0, acc[i][0]);
                acc[i][1] = fmaf(a, b1, acc[i][1]);
                acc[i][2] = fmaf(a, b2, acc[i][2]);
                acc[i][3] = fmaf(a, b3, acc[i][3]);
            }
        }
    }

    float bv[4];
#pragma unroll
    for (int c = 0; c < 4; c++) bv[c] = bias ? bias[bn + lane + 32 * c] : 0.f;
    float psum[4] = {0.f, 0.f, 0.f, 0.f}, psq[4] = {0.f, 0.f, 0.f, 0.f};
#pragma unroll
    for (int i = 0; i < 8; i++) {
        int gr = bm + rg + i;
        if (gr < M) {
#pragma unroll
            for (int c = 0; c < 4; c++) {
                float v = acc[i][c] + bv[c];
                if (do_relu) v = fmaxf(v, 0.f);
                out[(size_t)gr * ldout + bn + lane + 32 * c] = v;
                psum[c] += v;
                psq[c] += v * v;
            }
        }
    }
    if (stats) {
        __syncthreads();
        float* s_sum = sm;
        float* s_sq = sm + 128;
        if (tid < 128) { s_sum[tid] = 0.f; s_sq[tid] = 0.f; }
        __syncthreads();
#pragma unroll
        for (int c = 0; c < 4; c++) {
            atomicAdd(&s_sum[lane + 32 * c], psum[c]);
            atomicAdd(&s_sq[lane + 32 * c], psq[c]);
        }
        __syncthreads();
        if (tid < 128) {
            atomicAdd(&stats[tid], s_sum[tid]);
            atomicAdd(&stats[128 + tid], s_sq[tid]);
        }
    }
}

// ---------------- BN stats finalize ----------------
__global__ void finalize_stats(float* stats, const float* __restrict__ gamma,
                               const float* __restrict__ beta, float invN) {
    int j = threadIdx.x;
    float s = stats[j], sq = stats[128 + j];
    float mu = s * invN;
    float var = fmaxf(sq * invN - mu * mu, 0.f);
    float rstd = rsqrtf(var + 1e-5f);
    float sc = rstd * gamma[j];
    stats[j] = sc;
    stats[128 + j] = beta[j] - mu * sc;
}

// ---------------- BN apply + residual ----------------
__global__ void bn_res_kernel(const float4* __restrict__ hin, const float4* __restrict__ z,
                              const float* __restrict__ ss, float4* __restrict__ hout, int n4) {
    int i = blockIdx.x * blockDim.x + threadIdx.x;
    int stride = gridDim.x * blockDim.x;
    for (; i < n4; i += stride) {
        int j4 = i & 31;
        float4 zv = z[i];
        float4 hv = hin[i];
        float4 sc = ((const float4*)ss)[j4];
        float4 sh = ((const float4*)(ss + 128))[j4];
        float4 o;
        o.x = hv.x + zv.x * sc.x + sh.x;
        o.y = hv.y + zv.y * sc.y + sh.y;
        o.z = hv.z + zv.z * sc.z + sh.z;
        o.w = hv.w + zv.w * sc.w + sh.w;
        hout[i] = o;
    }
}

// ---------------- context attention pooling -> qin[b][0:128] ----------------
__global__ void attn_kernel(const int* __restrict__ ctx_ids, const float* __restrict__ emb,
                            const float* __restrict__ attn_w, const float* __restrict__ attn_b,
                            float* __restrict__ qin) {
    __shared__ float s_ctx[CTX_LEN * D];
    __shared__ float s_aw[D];
    __shared__ float s_logit[64];
    __shared__ float s_wt[64];
    int b = blockIdx.x;
    int tid = threadIdx.x;          // 128 threads
    int lane = tid & 31, wid = tid >> 5;
    s_aw[tid] = attn_w[tid];
    for (int i = tid; i < CTX_LEN * D; i += 128) {
        int l = i >> 7, d = i & 127;
        int id = ctx_ids[b * CTX_LEN + l];
        s_ctx[i] = emb[(size_t)id * D + d];
    }
    __syncthreads();
    for (int l = wid; l < CTX_LEN; l += 4) {
        float p = 0.f;
#pragma unroll
        for (int c = 0; c < 4; c++)
            p += s_ctx[l * D + lane + 32 * c] * s_aw[lane + 32 * c];
#pragma unroll
        for (int off = 16; off; off >>= 1) p += __shfl_xor_sync(0xffffffffu, p, off);
        if (lane == 0) s_logit[l] = p + attn_b[0];
    }
    __syncthreads();
    if (wid == 0) {
        float x0 = (lane < CTX_LEN) ? s_logit[lane] : -1e30f;
        float x1 = (lane + 32 < CTX_LEN) ? s_logit[lane + 32] : -1e30f;
        float m = fmaxf(x0, x1);
#pragma unroll
        for (int off = 16; off; off >>= 1) m = fmaxf(m, __shfl_xor_sync(0xffffffffu, m, off));
        float e0 = (lane < CTX_LEN) ? expf(x0 - m) : 0.f;
        float e1 = (lane + 32 < CTX_LEN) ? expf(x1 - m) : 0.f;
        float s = e0 + e1;
#pragma unroll
        for (int off = 16; off; off >>= 1) s += __shfl_xor_sync(0xffffffffu, s, off);
        float inv = 1.f / s;
        if (lane < CTX_LEN) s_wt[lane] = e0 * inv;
        if (lane + 32 < CTX_LEN) s_wt[lane + 32] = e1 * inv;
    }
    __syncthreads();
    float acc = 0.f;
    for (int l = 0; l < CTX_LEN; l++) acc += s_wt[l] * s_ctx[l * D + tid];
    qin[b * 256 + tid] = acc;
}

// ---------------- build fusion input ----------------
__global__ void miss_in_kernel(const int* __restrict__ miss_ids, const int* __restrict__ v2fg,
                               const float* __restrict__ emb, const float* __restrict__ graph,
                               float* __restrict__ in256) {
    int idx = blockIdx.x * blockDim.x + threadIdx.x;
    int b = idx >> 7, d = idx & 127;
    if (b >= BATCH) return;
    int mid = miss_ids[b];
    in256[b * 256 + d] = emb[(size_t)mid * D + d];
    int fg = v2fg[mid];
    in256[b * 256 + 128 + d] = (fg >= 0) ? graph[(size_t)fg * D + d] : 0.f;
}

// ---------------- launch ----------------
extern "C" void kernel_launch(void* const* d_in, const int* in_sizes, int n_in,
                              void* d_out, int out_size) {
    const int*   edge_index = (const int*)d_in[0];
    const float* norm       = (const float*)d_in[1];
    const int*   ctx_ids    = (const int*)d_in[2];
    const int*   miss_ids   = (const int*)d_in[3];
    const int*   v2fg       = (const int*)d_in[4];
    const float* emb_table  = (const float*)d_in[5];
    const float* fg_emb     = (const float*)d_in[6];
    const float* gc_w       = (const float*)d_in[7];
    const float* bn_gamma   = (const float*)d_in[8];
    const float* bn_beta    = (const float*)d_in[9];
    const float* attn_w     = (const float*)d_in[10];
    const float* attn_b     = (const float*)d_in[11];
    const float* fusion_w   = (const float*)d_in[12];
    const float* fusion_b   = (const float*)d_in[13];
    const float* proj1_w    = (const float*)d_in[14];
    const float* proj1_b    = (const float*)d_in[15];
    const float* proj2_w    = (const float*)d_in[16];
    const float* proj2_b    = (const float*)d_in[17];

    float* out   = (float*)d_out;
    float* query = out;                       // [1024,128]
    float* graph = out + (size_t)BATCH * D;   // [50000,128]

    float *agg, *z, *h, *in256, *qin, *q1, *stats;
    int *deg, *offs, *cursor;
    int2 *ep;
    cudaGetSymbolAddress((void**)&agg,    g_agg);
    cudaGetSymbolAddress((void**)&z,      g_z);
    cudaGetSymbolAddress((void**)&h,      g_h);
    cudaGetSymbolAddress((void**)&in256,  g_in256);
    cudaGetSymbolAddress((void**)&qin,    g_qin);
    cudaGetSymbolAddress((void**)&q1,     g_q1);
    cudaGetSymbolAddress((void**)&stats,  g_stats);
    cudaGetSymbolAddress((void**)&deg,    g_deg);
    cudaGetSymbolAddress((void**)&offs,   g_offs);
    cudaGetSymbolAddress((void**)&cursor, g_cursor);
    cudaGetSymbolAddress((void**)&ep,     g_epack);

    cudaFuncSetAttribute(gemm_kernel, cudaFuncAttributeMaxDynamicSharedMemorySize, GEMM_SMEM);

    const int* rows = edge_index;
    const int* cols = edge_index + N_EDGES;
    const int total4 = N_NODES * (D / 4);     // 1.6M float4

    // CSR build (once per call; shared by both layers)
    cudaMemsetAsync(deg, 0, N_NODES * sizeof(int), 0);
    cudaMemsetAsync(stats, 0, 512 * sizeof(float), 0);
    hist_kernel<<<3125, 256>>>(rows, deg);
    scan_kernel<<<1, 1024>>>((const int4*)deg, offs, cursor);
    permute_kernel<<<3125, 256>>>(rows, cols, norm, cursor, ep);

    // batch-side attention (independent of graph path)
    attn_kernel<<<BATCH, 128>>>(ctx_ids, emb_table, attn_w, attn_b, qin);

    // GCN layers
    for (int l = 0; l < 2; l++) {
        const float* hin = (l == 0) ? fg_emb : h;
        float* lstats = stats + l * 256;
        gather_kernel<<<6250, 256>>>(offs, ep, hin, agg);
        gemm_kernel<<<dim3(782, 1), 256, GEMM_SMEM>>>(agg, gc_w + (size_t)l * D * D, nullptr, z,
                                                      N_NODES, D, D, D, 1, lstats);
        finalize_stats<<<1, 128>>>(lstats, bn_gamma + l * D, bn_beta + l * D, 1.0f / N_NODES);
        float* hout = (l == 0) ? h : graph;
        bn_res_kernel<<<6250, 256>>>((const float4*)hin, (const float4*)z, lstats,
                                     (float4*)hout, total4);
    }

    // fusion + projection MLP
    miss_in_kernel<<<BATCH, 128>>>(miss_ids, v2fg, emb_table, graph, in256);
    gemm_kernel<<<dim3(16, 1), 256, GEMM_SMEM>>>(in256, fusion_w, fusion_b, qin + 128,
                                                 BATCH, 128, 256, 256, 0, nullptr);
    gemm_kernel<<<dim3(16, 2), 256, GEMM_SMEM>>>(qin, proj1_w, proj1_b, q1,
                                                 BATCH, 256, 256, 256, 1, nullptr);
    gemm_kernel<<<dim3(16, 1), 256, GEMM_SMEM>>>(q1, proj2_w, proj2_b, query,
                                                 BATCH, 128, 256, 128, 0, nullptr);
}

// round 11
// speedup vs baseline: 1.1036x; 1.0120x over previous
#include <cuda_runtime.h>
#include <cstdint>

#define N_NODES 50000
#define N_EDGES 800000
#define D 128
#define VOCAB 30000
#define BATCH 1024
#define CTX_LEN 50

// ---------------- scratch (no allocations allowed) ----------------
__device__ float g_agg[(size_t)N_NODES * D];
__device__ float g_z[(size_t)N_NODES * D];
__device__ float g_h[(size_t)N_NODES * D];
__device__ float g_in256[BATCH * 256];
__device__ float g_qin[BATCH * 256];
__device__ float g_q1[BATCH * 256];
__device__ float g_stats[512];           // 2 layers x (sum[128], sumsq[128])
__device__ int   g_deg[N_NODES];
__device__ int   g_offs[N_NODES + 4];
__device__ int   g_cursor[N_NODES];
__device__ int2  g_epack[N_EDGES];       // {col, bitcast(norm)}

// ---------------- histogram of edge rows ----------------
__global__ void hist_kernel(const int* __restrict__ rows, int* __restrict__ deg) {
    int e = blockIdx.x * blockDim.x + threadIdx.x;
    if (e < N_EDGES) atomicAdd(&deg[rows[e]], 1);
}

// ---------------- exclusive scan of deg -> offs, cursor (single block, int4) --------
__device__ __forceinline__ int warp_incl_scan(int v, int lane) {
#pragma unroll
    for (int o = 1; o < 32; o <<= 1) {
        int t = __shfl_up_sync(0xffffffffu, v, o);
        if (lane >= o) v += t;
    }
    return v;
}

#define N4 (N_NODES / 4)                 // 12500 int4 groups (N_NODES % 4 == 0)

__global__ void scan_kernel(const int4* __restrict__ deg4, int* __restrict__ offs,
                            int* __restrict__ cursor) {
    __shared__ int s_w[32];
    __shared__ int s_ws[32];
    __shared__ int s_carry;
    int tid = threadIdx.x;               // 1024 threads; 4 elems/thread/iter
    int lane = tid & 31, wid = tid >> 5;
    if (tid == 0) s_carry = 0;
    __syncthreads();
    for (int base = 0; base < N4; base += 1024) {
        int i4 = base + tid;
        int4 v = make_int4(0, 0, 0, 0);
        if (i4 < N4) v = deg4[i4];
        int tsum = v.x + v.y + v.z + v.w;
        int ws = warp_incl_scan(tsum, lane);
        if (lane == 31) s_w[wid] = ws;
        __syncthreads();
        if (wid == 0) s_ws[lane] = warp_incl_scan(s_w[lane], lane);
        __syncthreads();
        int excl = s_carry + ws - tsum + (wid ? s_ws[wid - 1] : 0);
        if (i4 < N4) {
            int o0 = excl;
            int o1 = o0 + v.x;
            int o2 = o1 + v.y;
            int o3 = o2 + v.z;
            int i = i4 * 4;
            offs[i] = o0; offs[i + 1] = o1; offs[i + 2] = o2; offs[i + 3] = o3;
            cursor[i] = o0; cursor[i + 1] = o1; cursor[i + 2] = o2; cursor[i + 3] = o3;
        }
        __syncthreads();
        if (tid == 0) s_carry += s_ws[31];
        __syncthreads();
    }
    if (tid == 0) offs[N_NODES] = s_carry;   // == N_EDGES
}

// ---------------- counting-sort permute: packed (col, norm) grouped by row ----------
__global__ void permute_kernel(const int* __restrict__ rows, const int* __restrict__ cols,
                               const float* __restrict__ norm, int* __restrict__ cursor,
                               int2* __restrict__ ep) {
    int e = blockIdx.x * blockDim.x + threadIdx.x;
    if (e >= N_EDGES) return;
    int r = rows[e];
    int pos = atomicAdd(&cursor[r], 1);
    ep[pos] = make_int2(cols[e], __float_as_int(norm[e]));
}

// ---------------- CSR gather: agg[i] = sum_e norm_e * h[col_e]  (no atomics) ----------
__global__ void gather_kernel(const int* __restrict__ offs, const int2* __restrict__ ep,
                              const float* __restrict__ h, float* __restrict__ agg) {
    int warp = blockIdx.x * (blockDim.x >> 5) + (threadIdx.x >> 5);
    if (warp >= N_NODES) return;
    int lane = threadIdx.x & 31;
    int e = offs[warp], end = offs[warp + 1];
    float4 a0 = make_float4(0.f, 0.f, 0.f, 0.f);
    float4 a1 = make_float4(0.f, 0.f, 0.f, 0.f);
    float4 a2 = make_float4(0.f, 0.f, 0.f, 0.f);
    float4 a3 = make_float4(0.f, 0.f, 0.f, 0.f);
    for (; e + 3 < end; e += 4) {
        int2 p0 = ep[e],     p1 = ep[e + 1];
        int2 p2 = ep[e + 2], p3 = ep[e + 3];
        float w0 = __int_as_float(p0.y), w1 = __int_as_float(p1.y);
        float w2 = __int_as_float(p2.y), w3 = __int_as_float(p3.y);
        float4 v0 = *((const float4*)(h + (size_t)p0.x * D) + lane);
        float4 v1 = *((const float4*)(h + (size_t)p1.x * D) + lane);
        float4 v2 = *((const float4*)(h + (size_t)p2.x * D) + lane);
        float4 v3 = *((const float4*)(h + (size_t)p3.x * D) + lane);
        a0.x = fmaf(w0, v0.x, a0.x); a0.y = fmaf(w0, v0.y, a0.y);
        a0.z = fmaf(w0, v0.z, a0.z); a0.w = fmaf(w0, v0.w, a0.w);
        a1.x = fmaf(w1, v1.x, a1.x); a1.y = fmaf(w1, v1.y, a1.y);
        a1.z = fmaf(w1, v1.z, a1.z); a1.w = fmaf(w1, v1.w, a1.w);
        a2.x = fmaf(w2, v2.x, a2.x); a2.y = fmaf(w2, v2.y, a2.y);
        a2.z = fmaf(w2, v2.z, a2.z); a2.w = fmaf(w2, v2.w, a2.w);
        a3.x = fmaf(w3, v3.x, a3.x); a3.y = fmaf(w3, v3.y, a3.y);
        a3.z = fmaf(w3, v3.z, a3.z); a3.w = fmaf(w3, v3.w, a3.w);
    }
    for (; e < end; e++) {
        int2 p0 = ep[e];
        float w0 = __int_as_float(p0.y);
        float4 v0 = *((const float4*)(h + (size_t)p0.x * D) + lane);
        a0.x = fmaf(w0, v0.x, a0.x); a0.y = fmaf(w0, v0.y, a0.y);
        a0.z = fmaf(w0, v0.z, a0.z); a0.w = fmaf(w0, v0.w, a0.w);
    }
    a0.x += a1.x; a0.y += a1.y; a0.z += a1.z; a0.w += a1.w;
    a2.x += a3.x; a2.y += a3.y; a2.z += a3.z; a2.w += a3.w;
    a0.x += a2.x; a0.y += a2.y; a0.z += a2.z; a0.w += a2.w;
    *((float4*)(agg + (size_t)warp * D) + lane) = a0;
}

// ========== tf32x3 tensor-core node GEMM: z = relu(A @ W^T), stats += (sum,sumsq) ====
// Block 256 threads = 8 warps; tile M=64, N=128, K=128 (single chunk).
// Warp (w&3) owns m-frag row (w&3)*16; (w>>2) owns n-half (w>>2)*64 (8 n8-frags).
// tf32x3: acc += Ahi*Blo + Alo*Bhi + Ahi*Bhi  (fp32-class accuracy).
#define SA 132                                   // smem stride: bank-conflict-free frags
#define TF_SMEM ((64 * SA + 128 * SA) * 4)       // 101376 bytes

__device__ __forceinline__ uint32_t f2tf32(float x) {
    uint32_t r;
    asm("cvt.rna.tf32.f32 %0, %1;" : "=r"(r) : "f"(x));
    return r;
}

#define MMA_TF32(c, a0, a1, a2, a3, b0, b1)                                       \
    asm volatile("mma.sync.aligned.m16n8k8.row.col.f32.tf32.tf32.f32 "            \
                 "{%0,%1,%2,%3}, {%4,%5,%6,%7}, {%8,%9}, {%0,%1,%2,%3};"          \
                 : "+f"((c)[0]), "+f"((c)[1]), "+f"((c)[2]), "+f"((c)[3])         \
                 : "r"(a0), "r"(a1), "r"(a2), "r"(a3), "r"(b0), "r"(b1))

__global__ void __launch_bounds__(256, 2)
gcn_gemm_tf32(const float* __restrict__ A, const float* __restrict__ W,
              float* __restrict__ z, float* __restrict__ stats, int M) {
    extern __shared__ float sm[];
    float* sA = sm;               // [64][SA]
    float* sB = sm + 64 * SA;     // [128][SA]
    int tid = threadIdx.x;
    int lane = tid & 31, wid = tid >> 5;
    int bm = blockIdx.x * 64;

    // A tile 64x128 (zero-pad rows >= M)
    for (int i = tid; i < 64 * 32; i += 256) {
        int r = i >> 5, c4 = i & 31;
        int gr = bm + r;
        float4 v = make_float4(0.f, 0.f, 0.f, 0.f);
        if (gr < M) v = *(const float4*)(A + (size_t)gr * D + c4 * 4);
        *(float4*)(sA + r * SA + c4 * 4) = v;
    }
    // W tile 128x128, natural [n][k]
    for (int i = tid; i < 128 * 32; i += 256) {
        int n = i >> 5, k4 = i & 31;
        *(float4*)(sB + n * SA + k4 * 4) = *(const float4*)(W + (size_t)n * D + k4 * 4);
    }
    __syncthreads();

    int mbase = (wid & 3) * 16;
    int nbase = (wid >> 2) * 64;
    int row = lane >> 2, kc = lane & 3;

    float acc[8][4];
#pragma unroll
    for (int nf = 0; nf < 8; nf++)
#pragma unroll
        for (int c = 0; c < 4; c++) acc[nf][c] = 0.f;

#pragma unroll 1
    for (int ks = 0; ks < 16; ks++) {
        int k0 = ks * 8;
        float af0 = sA[(mbase + row) * SA + k0 + kc];
        float af1 = sA[(mbase + row + 8) * SA + k0 + kc];
        float af2 = sA[(mbase + row) * SA + k0 + kc + 4];
        float af3 = sA[(mbase + row + 8) * SA + k0 + kc + 4];
        uint32_t ah0 = f2tf32(af0), ah1 = f2tf32(af1), ah2 = f2tf32(af2), ah3 = f2tf32(af3);
        uint32_t al0 = f2tf32(af0 - __uint_as_float(ah0));
        uint32_t al1 = f2tf32(af1 - __uint_as_float(ah1));
        uint32_t al2 = f2tf32(af2 - __uint_as_float(ah2));
        uint32_t al3 = f2tf32(af3 - __uint_as_float(ah3));
#pragma unroll
        for (int nf = 0; nf < 8; nf++) {
            int ncol = nbase + nf * 8 + row;
            float bf0 = sB[ncol * SA + k0 + kc];
            float bf1 = sB[ncol * SA + k0 + kc + 4];
            uint32_t bh0 = f2tf32(bf0), bh1 = f2tf32(bf1);
            uint32_t bl0 = f2tf32(bf0 - __uint_as_float(bh0));
            uint32_t bl1 = f2tf32(bf1 - __uint_as_float(bh1));
            MMA_TF32(acc[nf], ah0, ah1, ah2, ah3, bl0, bl1);
            MMA_TF32(acc[nf], al0, al1, al2, al3, bh0, bh1);
            MMA_TF32(acc[nf], ah0, ah1, ah2, ah3, bh0, bh1);
        }
    }
    __syncthreads();

    // stage acc -> sOut (reuse sA region; warps write disjoint m16 x n64 blocks)
    float* sOut = sm;
#pragma unroll
    for (int nf = 0; nf < 8; nf++) {
        int r0 = mbase + row;
        int c0 = nbase + nf * 8 + 2 * kc;
        sOut[r0 * SA + c0]           = acc[nf][0];
        sOut[r0 * SA + c0 + 1]       = acc[nf][1];
        sOut[(r0 + 8) * SA + c0]     = acc[nf][2];
        sOut[(r0 + 8) * SA + c0 + 1] = acc[nf][3];
    }
    __syncthreads();

    // epilogue: relu, coalesced z store, BN partial stats
    int rg = wid * 8;
    float psum[4] = {0.f, 0.f, 0.f, 0.f}, psq[4] = {0.f, 0.f, 0.f, 0.f};
#pragma unroll
    for (int i = 0; i < 8; i++) {
        int gr = bm + rg + i;
        if (gr < M) {
#pragma unroll
            for (int c = 0; c < 4; c++) {
                float v = fmaxf(sOut[(rg + i) * SA + lane + 32 * c], 0.f);
                z[(size_t)gr * D + lane + 32 * c] = v;
                psum[c] += v;
                psq[c] += v * v;
            }
        }
    }
    __syncthreads();
    float* s_sum = sm;
    float* s_sq = sm + 128;
    if (tid < 128) { s_sum[tid] = 0.f; s_sq[tid] = 0.f; }
    __syncthreads();
#pragma unroll
    for (int c = 0; c < 4; c++) {
        atomicAdd(&s_sum[lane + 32 * c], psum[c]);
        atomicAdd(&s_sq[lane + 32 * c], psq[c]);
    }
    __syncthreads();
    if (tid < 128) {
        atomicAdd(&stats[tid], s_sum[tid]);
        atomicAdd(&stats[128 + tid], s_sq[tid]);
    }
}

// ---------------- generic GEMM (batch MLP): out = act(A @ W^T + bias) ----------------
#define SBK 129
#define GEMM_SMEM ((64 * 128 + 128 * SBK) * 4)

__global__ void __launch_bounds__(256, 2)
gemm_kernel(const float* __restrict__ A, const float* __restrict__ W,
            const float* __restrict__ bias, float* __restrict__ out,
            int M, int N, int K, int ldout, int do_relu) {
    extern __shared__ float sm[];
    float* sA = sm;
    float* sB = sm + 64 * 128;
    int tid = threadIdx.x;
    int lane = tid & 31, wid = tid >> 5;
    int bm = blockIdx.x * 64;
    int bn = blockIdx.y * 128;

    float acc[8][4];
#pragma unroll
    for (int i = 0; i < 8; i++)
#pragma unroll
        for (int c = 0; c < 4; c++) acc[i][c] = 0.f;

    int rg = wid * 8;
    for (int k0 = 0; k0 < K; k0 += 128) {
        __syncthreads();
        for (int i = tid; i < 64 * 32; i += 256) {
            int r = i >> 5, c4 = i & 31;
            int gr = bm + r;
            float4 v = make_float4(0.f, 0.f, 0.f, 0.f);
            if (gr < M) v = *(const float4*)(A + (size_t)gr * K + k0 + c4 * 4);
            *(float4*)(sA + r * 128 + c4 * 4) = v;
        }
        for (int i = tid; i < 128 * 32; i += 256) {
            int n = i >> 5, k4 = i & 31;
            float4 v = *(const float4*)(W + (size_t)(bn + n) * K + k0 + k4 * 4);
            float* p = sB + n * SBK + k4 * 4;
            p[0] = v.x; p[1] = v.y; p[2] = v.z; p[3] = v.w;
        }
        __syncthreads();
#pragma unroll 4
        for (int k = 0; k < 128; k++) {
            float b0 = sB[(lane)      * SBK + k];
            float b1 = sB[(lane + 32) * SBK + k];
            float b2 = sB[(lane + 64) * SBK + k];
            float b3 = sB[(lane + 96) * SBK + k];
#pragma unroll
            for (int i = 0; i < 8; i++) {
                float a = sA[(rg + i) * 128 + k];
                acc[i][0] = fmaf(a, b0, acc[i][0]);
                acc[i][1] = fmaf(a, b1, acc[i][1]);
                acc[i][2] = fmaf(a, b2, acc[i][2]);
                acc[i][3] = fmaf(a, b3, acc[i][3]);
            }
        }
    }

    float bv[4];
#pragma unroll
    for (int c = 0; c < 4; c++) bv[c] = bias ? bias[bn + lane + 32 * c] : 0.f;
#pragma unroll
    for (int i = 0; i < 8; i++) {
        int gr = bm + rg + i;
        if (gr < M) {
#pragma unroll
            for (int c = 0; c < 4; c++) {
                float v = acc[i][c] + bv[c];
                if (do_relu) v = fmaxf(v, 0.f);
                out[(size_t)gr * ldout + bn + lane + 32 * c] = v;
            }
        }
    }
}

// ---------------- BN stats finalize ----------------
__global__ void finalize_stats(float* stats, const float* __restrict__ gamma,
                               const float* __restrict__ beta, float invN) {
    int j = threadIdx.x;
    float s = stats[j], sq = stats[128 + j];
    float mu = s * invN;
    float var = fmaxf(sq * invN - mu * mu, 0.f);
    float rstd = rsqrtf(var + 1e-5f);
    float sc = rstd * gamma[j];
    stats[j] = sc;
    stats[128 + j] = beta[j] - mu * sc;
}

// ---------------- BN apply + residual ----------------
__global__ void bn_res_kernel(const float4* __restrict__ hin, const float4* __restrict__ z,
                              const float* __restrict__ ss, float4* __restrict__ hout, int n4) {
    int i = blockIdx.x * blockDim.x + threadIdx.x;
    int stride = gridDim.x * blockDim.x;
    for (; i < n4; i += stride) {
        int j4 = i & 31;
        float4 zv = z[i];
        float4 hv = hin[i];
        float4 sc = ((const float4*)ss)[j4];
        float4 sh = ((const float4*)(ss + 128))[j4];
        float4 o;
        o.x = hv.x + zv.x * sc.x + sh.x;
        o.y = hv.y + zv.y * sc.y + sh.y;
        o.z = hv.z + zv.z * sc.z + sh.z;
        o.w = hv.w + zv.w * sc.w + sh.w;
        hout[i] = o;
    }
}

// ---------------- context attention pooling -> qin[b][0:128] ----------------
__global__ void attn_kernel(const int* __restrict__ ctx_ids, const float* __restrict__ emb,
                            const float* __restrict__ attn_w, const float* __restrict__ attn_b,
                            float* __restrict__ qin) {
    __shared__ float s_ctx[CTX_LEN * D];
    __shared__ float s_aw[D];
    __shared__ float s_logit[64];
    __shared__ float s_wt[64];
    int b = blockIdx.x;
    int tid = threadIdx.x;          // 128 threads
    int lane = tid & 31, wid = tid >> 5;
    s_aw[tid] = attn_w[tid];
    for (int i = tid; i < CTX_LEN * D; i += 128) {
        int l = i >> 7, d = i & 127;
        int id = ctx_ids[b * CTX_LEN + l];
        s_ctx[i] = emb[(size_t)id * D + d];
    }
    __syncthreads();
    for (int l = wid; l < CTX_LEN; l += 4) {
        float p = 0.f;
#pragma unroll
        for (int c = 0; c < 4; c++)
            p += s_ctx[l * D + lane + 32 * c] * s_aw[lane + 32 * c];
#pragma unroll
        for (int off = 16; off; off >>= 1) p += __shfl_xor_sync(0xffffffffu, p, off);
        if (lane == 0) s_logit[l] = p + attn_b[0];
    }
    __syncthreads();
    if (wid == 0) {
        float x0 = (lane < CTX_LEN) ? s_logit[lane] : -1e30f;
        float x1 = (lane + 32 < CTX_LEN) ? s_logit[lane + 32] : -1e30f;
        float m = fmaxf(x0, x1);
#pragma unroll
        for (int off = 16; off; off >>= 1) m = fmaxf(m, __shfl_xor_sync(0xffffffffu, m, off));
        float e0 = (lane < CTX_LEN) ? expf(x0 - m) : 0.f;
        float e1 = (lane + 32 < CTX_LEN) ? expf(x1 - m) : 0.f;
        float s = e0 + e1;
#pragma unroll
        for (int off = 16; off; off >>= 1) s += __shfl_xor_sync(0xffffffffu, s, off);
        float inv = 1.f / s;
        if (lane < CTX_LEN) s_wt[lane] = e0 * inv;
        if (lane + 32 < CTX_LEN) s_wt[lane + 32] = e1 * inv;
    }
    __syncthreads();
    float acc = 0.f;
    for (int l = 0; l < CTX_LEN; l++) acc += s_wt[l] * s_ctx[l * D + tid];
    qin[b * 256 + tid] = acc;
}

// ---------------- build fusion input ----------------
__global__ void miss_in_kernel(const int* __restrict__ miss_ids, const int* __restrict__ v2fg,
                               const float* __restrict__ emb, const float* __restrict__ graph,
                               float* __restrict__ in256) {
    int idx = blockIdx.x * blockDim.x + threadIdx.x;
    int b = idx >> 7, d = idx & 127;
    if (b >= BATCH) return;
    int mid = miss_ids[b];
    in256[b * 256 + d] = emb[(size_t)mid * D + d];
    int fg = v2fg[mid];
    in256[b * 256 + 128 + d] = (fg >= 0) ? graph[(size_t)fg * D + d] : 0.f;
}

// ---------------- launch ----------------
extern "C" void kernel_launch(void* const* d_in, const int* in_sizes, int n_in,
                              void* d_out, int out_size) {
    const int*   edge_index = (const int*)d_in[0];
    const float* norm       = (const float*)d_in[1];
    const int*   ctx_ids    = (const int*)d_in[2];
    const int*   miss_ids   = (const int*)d_in[3];
    const int*   v2fg       = (const int*)d_in[4];
    const float* emb_table  = (const float*)d_in[5];
    const float* fg_emb     = (const float*)d_in[6];
    const float* gc_w       = (const float*)d_in[7];
    const float* bn_gamma   = (const float*)d_in[8];
    const float* bn_beta    = (const float*)d_in[9];
    const float* attn_w     = (const float*)d_in[10];
    const float* attn_b     = (const float*)d_in[11];
    const float* fusion_w   = (const float*)d_in[12];
    const float* fusion_b   = (const float*)d_in[13];
    const float* proj1_w    = (const float*)d_in[14];
    const float* proj1_b    = (const float*)d_in[15];
    const float* proj2_w    = (const float*)d_in[16];
    const float* proj2_b    = (const float*)d_in[17];

    float* out   = (float*)d_out;
    float* query = out;                       // [1024,128]
    float* graph = out + (size_t)BATCH * D;   // [50000,128]

    float *agg, *z, *h, *in256, *qin, *q1, *stats;
    int *deg, *offs, *cursor;
    int2 *ep;
    cudaGetSymbolAddress((void**)&agg,    g_agg);
    cudaGetSymbolAddress((void**)&z,      g_z);
    cudaGetSymbolAddress((void**)&h,      g_h);
    cudaGetSymbolAddress((void**)&in256,  g_in256);
    cudaGetSymbolAddress((void**)&qin,    g_qin);
    cudaGetSymbolAddress((void**)&q1,     g_q1);
    cudaGetSymbolAddress((void**)&stats,  g_stats);
    cudaGetSymbolAddress((void**)&deg,    g_deg);
    cudaGetSymbolAddress((void**)&offs,   g_offs);
    cudaGetSymbolAddress((void**)&cursor, g_cursor);
    cudaGetSymbolAddress((void**)&ep,     g_epack);

    cudaFuncSetAttribute(gemm_kernel, cudaFuncAttributeMaxDynamicSharedMemorySize, GEMM_SMEM);
    cudaFuncSetAttribute(gcn_gemm_tf32, cudaFuncAttributeMaxDynamicSharedMemorySize, TF_SMEM);

    const int* rows = edge_index;
    const int* cols = edge_index + N_EDGES;
    const int total4 = N_NODES * (D / 4);     // 1.6M float4

    // CSR build (once per call; shared by both layers)
    cudaMemsetAsync(deg, 0, N_NODES * sizeof(int), 0);
    cudaMemsetAsync(stats, 0, 512 * sizeof(float), 0);
    hist_kernel<<<3125, 256>>>(rows, deg);
    scan_kernel<<<1, 1024>>>((const int4*)deg, offs, cursor);
    permute_kernel<<<3125, 256>>>(rows, cols, norm, cursor, ep);

    // batch-side attention (independent of graph path)
    attn_kernel<<<BATCH, 128>>>(ctx_ids, emb_table, attn_w, attn_b, qin);

    // GCN layers
    for (int l = 0; l < 2; l++) {
        const float* hin = (l == 0) ? fg_emb : h;
        float* lstats = stats + l * 256;
        gather_kernel<<<6250, 256>>>(offs, ep, hin, agg);
        gcn_gemm_tf32<<<782, 256, TF_SMEM>>>(agg, gc_w + (size_t)l * D * D, z, lstats, N_NODES);
        finalize_stats<<<1, 128>>>(lstats, bn_gamma + l * D, bn_beta + l * D, 1.0f / N_NODES);
        float* hout = (l == 0) ? h : graph;
        bn_res_kernel<<<6250, 256>>>((const float4*)hin, (const float4*)z, lstats,
                                     (float4*)hout, total4);
    }

    // fusion + projection MLP
    miss_in_kernel<<<BATCH, 128>>>(miss_ids, v2fg, emb_table, graph, in256);
    gemm_kernel<<<dim3(16, 1), 256, GEMM_SMEM>>>(in256, fusion_w, fusion_b, qin + 128,
                                                 BATCH, 128, 256, 256, 0);
    gemm_kernel<<<dim3(16, 2), 256, GEMM_SMEM>>>(qin, proj1_w, proj1_b, q1,
                                                 BATCH, 256, 256, 256, 1);
    gemm_kernel<<<dim3(16, 1), 256, GEMM_SMEM>>>(q1, proj2_w, proj2_b, query,
                                                 BATCH, 128, 256, 128, 0);
}

// round 15
// speedup vs baseline: 1.1276x; 1.0218x over previous
#include <cuda_runtime.h>
#include <cstdint>

#define N_NODES 50000
#define N_EDGES 800000
#define D 128
#define VOCAB 30000
#define BATCH 1024
#define CTX_LEN 50

// ---------------- scratch (no allocations allowed) ----------------
__device__ float g_agg[(size_t)N_NODES * D];
__device__ float g_z[(size_t)N_NODES * D];
__device__ float g_h[(size_t)N_NODES * D];
__device__ float g_qin[BATCH * 256];
__device__ float g_q1[BATCH * 256];
__device__ float g_stats[512];           // 2 layers x (sum[128], sumsq[128])
__device__ int   g_deg[N_NODES];
__device__ int   g_offs[N_NODES + 4];
__device__ int   g_cursor[N_NODES];
__device__ int2  g_epack[N_EDGES];       // {col, bitcast(norm)}

// ---------------- histogram of edge rows (+ zero BOTH BN stats banks) ----------------
__global__ void hist_kernel(const int* __restrict__ rows, int* __restrict__ deg,
                            float* __restrict__ stats) {
    int e = blockIdx.x * blockDim.x + threadIdx.x;
    if (blockIdx.x == 0 && threadIdx.x < 256) {      // blockDim.x == 256: zero all 512
        stats[threadIdx.x] = 0.f;
        stats[threadIdx.x + 256] = 0.f;
    }
    if (e < N_EDGES) atomicAdd(&deg[rows[e]], 1);
}

// ---------------- exclusive scan of deg -> offs, cursor (single block, int4) --------
__device__ __forceinline__ int warp_incl_scan(int v, int lane) {
#pragma unroll
    for (int o = 1; o < 32; o <<= 1) {
        int t = __shfl_up_sync(0xffffffffu, v, o);
        if (lane >= o) v += t;
    }
    return v;
}

#define N4 (N_NODES / 4)                 // 12500 int4 groups (N_NODES % 4 == 0)

__global__ void scan_kernel(const int4* __restrict__ deg4, int* __restrict__ offs,
                            int* __restrict__ cursor) {
    __shared__ int s_w[32];
    __shared__ int s_ws[32];
    __shared__ int s_carry;
    int tid = threadIdx.x;               // 1024 threads; 4 elems/thread/iter
    int lane = tid & 31, wid = tid >> 5;
    if (tid == 0) s_carry = 0;
    __syncthreads();
    for (int base = 0; base < N4; base += 1024) {
        int i4 = base + tid;
        int4 v = make_int4(0, 0, 0, 0);
        if (i4 < N4) v = deg4[i4];
        int tsum = v.x + v.y + v.z + v.w;
        int ws = warp_incl_scan(tsum, lane);
        if (lane == 31) s_w[wid] = ws;
        __syncthreads();
        if (wid == 0) s_ws[lane] = warp_incl_scan(s_w[lane], lane);
        __syncthreads();
        int excl = s_carry + ws - tsum + (wid ? s_ws[wid - 1] : 0);
        if (i4 < N4) {
            int o0 = excl;
            int o1 = o0 + v.x;
            int o2 = o1 + v.y;
            int o3 = o2 + v.z;
            int i = i4 * 4;
            offs[i] = o0; offs[i + 1] = o1; offs[i + 2] = o2; offs[i + 3] = o3;
            cursor[i] = o0; cursor[i + 1] = o1; cursor[i + 2] = o2; cursor[i + 3] = o3;
        }
        __syncthreads();
        if (tid == 0) s_carry += s_ws[31];
        __syncthreads();
    }
    if (tid == 0) offs[N_NODES] = s_carry;   // == N_EDGES
}

// ---------------- counting-sort permute: packed (col, norm) grouped by row ----------
__global__ void permute_kernel(const int* __restrict__ rows, const int* __restrict__ cols,
                               const float* __restrict__ norm, int* __restrict__ cursor,
                               int2* __restrict__ ep) {
    int e = blockIdx.x * blockDim.x + threadIdx.x;
    if (e >= N_EDGES) return;
    int r = rows[e];
    int pos = atomicAdd(&cursor[r], 1);
    ep[pos] = make_int2(cols[e], __float_as_int(norm[e]));
}

// ---------------- CSR gather: agg[i] = sum_e norm_e * h[col_e]  (no atomics) ----------
__global__ void gather_kernel(const int* __restrict__ offs, const int2* __restrict__ ep,
                              const float* __restrict__ h, float* __restrict__ agg) {
    int warp = blockIdx.x * (blockDim.x >> 5) + (threadIdx.x >> 5);
    if (warp >= N_NODES) return;
    int lane = threadIdx.x & 31;
    int e = offs[warp], end = offs[warp + 1];
    float4 a0 = make_float4(0.f, 0.f, 0.f, 0.f);
    float4 a1 = make_float4(0.f, 0.f, 0.f, 0.f);
    float4 a2 = make_float4(0.f, 0.f, 0.f, 0.f);
    float4 a3 = make_float4(0.f, 0.f, 0.f, 0.f);
    for (; e + 3 < end; e += 4) {
        int2 p0 = ep[e],     p1 = ep[e + 1];
        int2 p2 = ep[e + 2], p3 = ep[e + 3];
        float w0 = __int_as_float(p0.y), w1 = __int_as_float(p1.y);
        float w2 = __int_as_float(p2.y), w3 = __int_as_float(p3.y);
        float4 v0 = *((const float4*)(h + (size_t)p0.x * D) + lane);
        float4 v1 = *((const float4*)(h + (size_t)p1.x * D) + lane);
        float4 v2 = *((const float4*)(h + (size_t)p2.x * D) + lane);
        float4 v3 = *((const float4*)(h + (size_t)p3.x * D) + lane);
        a0.x = fmaf(w0, v0.x, a0.x); a0.y = fmaf(w0, v0.y, a0.y);
        a0.z = fmaf(w0, v0.z, a0.z); a0.w = fmaf(w0, v0.w, a0.w);
        a1.x = fmaf(w1, v1.x, a1.x); a1.y = fmaf(w1, v1.y, a1.y);
        a1.z = fmaf(w1, v1.z, a1.z); a1.w = fmaf(w1, v1.w, a1.w);
        a2.x = fmaf(w2, v2.x, a2.x); a2.y = fmaf(w2, v2.y, a2.y);
        a2.z = fmaf(w2, v2.z, a2.z); a2.w = fmaf(w2, v2.w, a2.w);
        a3.x = fmaf(w3, v3.x, a3.x); a3.y = fmaf(w3, v3.y, a3.y);
        a3.z = fmaf(w3, v3.z, a3.z); a3.w = fmaf(w3, v3.w, a3.w);
    }
    for (; e < end; e++) {
        int2 p0 = ep[e];
        float w0 = __int_as_float(p0.y);
        float4 v0 = *((const float4*)(h + (size_t)p0.x * D) + lane);
        a0.x = fmaf(w0, v0.x, a0.x); a0.y = fmaf(w0, v0.y, a0.y);
        a0.z = fmaf(w0, v0.z, a0.z); a0.w = fmaf(w0, v0.w, a0.w);
    }
    a0.x += a1.x; a0.y += a1.y; a0.z += a1.z; a0.w += a1.w;
    a2.x += a3.x; a2.y += a3.y; a2.z += a3.z; a2.w += a3.w;
    a0.x += a2.x; a0.y += a2.y; a0.z += a2.z; a0.w += a2.w;
    *((float4*)(agg + (size_t)warp * D) + lane) = a0;
}

// ========== tf32x3 tensor-core node GEMM: z = relu(A @ W^T), stats += (sum,sumsq) ====
#define SA 132                                   // smem stride: bank-conflict-free frags
#define TF_SMEM ((64 * SA + 128 * SA) * 4)       // 101376 bytes

__device__ __forceinline__ uint32_t f2tf32(float x) {
    uint32_t r;
    asm("cvt.rna.tf32.f32 %0, %1;" : "=r"(r) : "f"(x));
    return r;
}

#define MMA_TF32(c, a0, a1, a2, a3, b0, b1)                                       \
    asm volatile("mma.sync.aligned.m16n8k8.row.col.f32.tf32.tf32.f32 "            \
                 "{%0,%1,%2,%3}, {%4,%5,%6,%7}, {%8,%9}, {%0,%1,%2,%3};"          \
                 : "+f"((c)[0]), "+f"((c)[1]), "+f"((c)[2]), "+f"((c)[3])         \
                 : "r"(a0), "r"(a1), "r"(a2), "r"(a3), "r"(b0), "r"(b1))

__global__ void __launch_bounds__(256, 2)
gcn_gemm_tf32(const float* __restrict__ A, const float* __restrict__ W,
              float* __restrict__ z, float* __restrict__ stats, int M) {
    extern __shared__ float sm[];
    float* sA = sm;               // [64][SA]
    float* sB = sm + 64 * SA;     // [128][SA]
    int tid = threadIdx.x;
    int lane = tid & 31, wid = tid >> 5;
    int bm = blockIdx.x * 64;

    for (int i = tid; i < 64 * 32; i += 256) {
        int r = i >> 5, c4 = i & 31;
        int gr = bm + r;
        float4 v = make_float4(0.f, 0.f, 0.f, 0.f);
        if (gr < M) v = *(const float4*)(A + (size_t)gr * D + c4 * 4);
        *(float4*)(sA + r * SA + c4 * 4) = v;
    }
    for (int i = tid; i < 128 * 32; i += 256) {
        int n = i >> 5, k4 = i & 31;
        *(float4*)(sB + n * SA + k4 * 4) = *(const float4*)(W + (size_t)n * D + k4 * 4);
    }
    __syncthreads();

    int mbase = (wid & 3) * 16;
    int nbase = (wid >> 2) * 64;
    int row = lane >> 2, kc = lane & 3;

    float acc[8][4];
#pragma unroll
    for (int nf = 0; nf < 8; nf++)
#pragma unroll
        for (int c = 0; c < 4; c++) acc[nf][c] = 0.f;

#pragma unroll 1
    for (int ks = 0; ks < 16; ks++) {
        int k0 = ks * 8;
        float af0 = sA[(mbase + row) * SA + k0 + kc];
        float af1 = sA[(mbase + row + 8) * SA + k0 + kc];
        float af2 = sA[(mbase + row) * SA + k0 + kc + 4];
        float af3 = sA[(mbase + row + 8) * SA + k0 + kc + 4];
        uint32_t ah0 = f2tf32(af0), ah1 = f2tf32(af1), ah2 = f2tf32(af2), ah3 = f2tf32(af3);
        uint32_t al0 = f2tf32(af0 - __uint_as_float(ah0));
        uint32_t al1 = f2tf32(af1 - __uint_as_float(ah1));
        uint32_t al2 = f2tf32(af2 - __uint_as_float(ah2));
        uint32_t al3 = f2tf32(af3 - __uint_as_float(ah3));
#pragma unroll
        for (int nf = 0; nf < 8; nf++) {
            int ncol = nbase + nf * 8 + row;
            float bf0 = sB[ncol * SA + k0 + kc];
            float bf1 = sB[ncol * SA + k0 + kc + 4];
            uint32_t bh0 = f2tf32(bf0), bh1 = f2tf32(bf1);
            uint32_t bl0 = f2tf32(bf0 - __uint_as_float(bh0));
            uint32_t bl1 = f2tf32(bf1 - __uint_as_float(bh1));
            MMA_TF32(acc[nf], ah0, ah1, ah2, ah3, bl0, bl1);
            MMA_TF32(acc[nf], al0, al1, al2, al3, bh0, bh1);
            MMA_TF32(acc[nf], ah0, ah1, ah2, ah3, bh0, bh1);
        }
    }
    __syncthreads();

    float* sOut = sm;
#pragma unroll
    for (int nf = 0; nf < 8; nf++) {
        int r0 = mbase + row;
        int c0 = nbase + nf * 8 + 2 * kc;
        sOut[r0 * SA + c0]           = acc[nf][0];
        sOut[r0 * SA + c0 + 1]       = acc[nf][1];
        sOut[(r0 + 8) * SA + c0]     = acc[nf][2];
        sOut[(r0 + 8) * SA + c0 + 1] = acc[nf][3];
    }
    __syncthreads();

    int rg = wid * 8;
    float psum[4] = {0.f, 0.f, 0.f, 0.f}, psq[4] = {0.f, 0.f, 0.f, 0.f};
#pragma unroll
    for (int i = 0; i < 8; i++) {
        int gr = bm + rg + i;
        if (gr < M) {
#pragma unroll
            for (int c = 0; c < 4; c++) {
                float v = fmaxf(sOut[(rg + i) * SA + lane + 32 * c], 0.f);
                z[(size_t)gr * D + lane + 32 * c] = v;
                psum[c] += v;
                psq[c] += v * v;
            }
        }
    }
    __syncthreads();
    float* s_sum = sm;
    float* s_sq = sm + 128;
    if (tid < 128) { s_sum[tid] = 0.f; s_sq[tid] = 0.f; }
    __syncthreads();
#pragma unroll
    for (int c = 0; c < 4; c++) {
        atomicAdd(&s_sum[lane + 32 * c], psum[c]);
        atomicAdd(&s_sq[lane + 32 * c], psq[c]);
    }
    __syncthreads();
    if (tid < 128) {
        atomicAdd(&stats[tid], s_sum[tid]);
        atomicAdd(&stats[128 + tid], s_sq[tid]);
    }
}

// ---------------- generic GEMM (batch MLP): out = act(A @ W^T + bias) ----------------
#define SBK 129
#define GEMM_SMEM ((64 * 128 + 128 * SBK) * 4)

__global__ void __launch_bounds__(256, 2)
gemm_kernel(const float* __restrict__ A, const float* __restrict__ W,
            const float* __restrict__ bias, float* __restrict__ out,
            int M, int N, int K, int ldout, int do_relu) {
    extern __shared__ float sm[];
    float* sA = sm;
    float* sB = sm + 64 * 128;
    int tid = threadIdx.x;
    int lane = tid & 31, wid = tid >> 5;
    int bm = blockIdx.x * 64;
    int bn = blockIdx.y * 128;

    float acc[8][4];
#pragma unroll
    for (int i = 0; i < 8; i++)
#pragma unroll
        for (int c = 0; c < 4; c++) acc[i][c] = 0.f;

    int rg = wid * 8;
    for (int k0 = 0; k0 < K; k0 += 128) {
        __syncthreads();
        for (int i = tid; i < 64 * 32; i += 256) {
            int r = i >> 5, c4 = i & 31;
            int gr = bm + r;
            float4 v = make_float4(0.f, 0.f, 0.f, 0.f);
            if (gr < M) v = *(const float4*)(A + (size_t)gr * K + k0 + c4 * 4);
            *(float4*)(sA + r * 128 + c4 * 4) = v;
        }
        for (int i = tid; i < 128 * 32; i += 256) {
            int n = i >> 5, k4 = i & 31;
            float4 v = *(const float4*)(W + (size_t)(bn + n) * K + k0 + k4 * 4);
            float* p = sB + n * SBK + k4 * 4;
            p[0] = v.x; p[1] = v.y; p[2] = v.z; p[3] = v.w;
        }
        __syncthreads();
#pragma unroll 4
        for (int k = 0; k < 128; k++) {
            float b0 = sB[(lane)      * SBK + k];
            float b1 = sB[(lane + 32) * SBK + k];
            float b2 = sB[(lane + 64) * SBK + k];
            float b3 = sB[(lane + 96) * SBK + k];
#pragma unroll
            for (int i = 0; i < 8; i++) {
                float a = sA[(rg + i) * 128 + k];
                acc[i][0] = fmaf(a, b0, acc[i][0]);
                acc[i][1] = fmaf(a, b1, acc[i][1]);
                acc[i][2] = fmaf(a, b2, acc[i][2]);
                acc[i][3] = fmaf(a, b3, acc[i][3]);
            }
        }
    }

    float bv[4];
#pragma unroll
    for (int c = 0; c < 4; c++) bv[c] = bias ? bias[bn + lane + 32 * c] : 0.f;
#pragma unroll
    for (int i = 0; i < 8; i++) {
        int gr = bm + rg + i;
        if (gr < M) {
#pragma unroll
            for (int c = 0; c < 4; c++) {
                float v = acc[i][c] + bv[c];
                if (do_relu) v = fmaxf(v, 0.f);
                out[(size_t)gr * ldout + bn + lane + 32 * c] = v;
            }
        }
    }
}

// -------- fusion GEMM with inline gathered A: miss_emb = [emb[mid], mask*graph[fg]] @ W^T + b
__global__ void __launch_bounds__(256, 2)
fusion_gemm_kernel(const int* __restrict__ miss_ids, const int* __restrict__ v2fg,
                   const float* __restrict__ emb, const float* __restrict__ graph,
                   const float* __restrict__ W, const float* __restrict__ bias,
                   float* __restrict__ out) {
    // M=1024 (tile 64), N=128, K=256, ldout=256
    extern __shared__ float sm[];
    float* sA = sm;
    float* sB = sm + 64 * 128;
    int tid = threadIdx.x;
    int lane = tid & 31, wid = tid >> 5;
    int bm = blockIdx.x * 64;

    float acc[8][4];
#pragma unroll
    for (int i = 0; i < 8; i++)
#pragma unroll
        for (int c = 0; c < 4; c++) acc[i][c] = 0.f;

    int rg = wid * 8;
    for (int k0 = 0; k0 < 256; k0 += 128) {
        __syncthreads();
        for (int i = tid; i < 64 * 32; i += 256) {
            int r = i >> 5, c4 = i & 31;
            int gr = bm + r;
            int mid = miss_ids[gr];
            float4 v;
            if (k0 == 0) {
                v = *(const float4*)(emb + (size_t)mid * D + c4 * 4);
            } else {
                int fg = v2fg[mid];
                v = (fg >= 0) ? *(const float4*)(graph + (size_t)fg * D + c4 * 4)
                              : make_float4(0.f, 0.f, 0.f, 0.f);
            }
            *(float4*)(sA + r * 128 + c4 * 4) = v;
        }
        for (int i = tid; i < 128 * 32; i += 256) {
            int n = i >> 5, k4 = i & 31;
            float4 v = *(const float4*)(W + (size_t)n * 256 + k0 + k4 * 4);
            float* p = sB + n * SBK + k4 * 4;
            p[0] = v.x; p[1] = v.y; p[2] = v.z; p[3] = v.w;
        }
        __syncthreads();
#pragma unroll 4
        for (int k = 0; k < 128; k++) {
            float b0 = sB[(lane)      * SBK + k];
            float b1 = sB[(lane + 32) * SBK + k];
            float b2 = sB[(lane + 64) * SBK + k];
            float b3 = sB[(lane + 96) * SBK + k];
#pragma unroll
            for (int i = 0; i < 8; i++) {
                float a = sA[(rg + i) * 128 + k];
                acc[i][0] = fmaf(a, b0, acc[i][0]);
                acc[i][1] = fmaf(a, b1, acc[i][1]);
                acc[i][2] = fmaf(a, b2, acc[i][2]);
                acc[i][3] = fmaf(a, b3, acc[i][3]);
            }
        }
    }

    float bv[4];
#pragma unroll
    for (int c = 0; c < 4; c++) bv[c] = bias[lane + 32 * c];
#pragma unroll
    for (int i = 0; i < 8; i++) {
        int gr = bm + rg + i;
#pragma unroll
        for (int c = 0; c < 4; c++)
            out[(size_t)gr * 256 + lane + 32 * c] = acc[i][c] + bv[c];
    }
}

// ---------------- BN apply + residual (computes scale/shift from raw stats) ---------
__global__ void bn_res_kernel(const float4* __restrict__ hin, const float4* __restrict__ z,
                              const float* __restrict__ stats, const float* __restrict__ gamma,
                              const float* __restrict__ beta, float4* __restrict__ hout,
                              int n4) {
    __shared__ float s_sc[128];
    __shared__ float s_sh[128];
    int tid = threadIdx.x;
    if (tid < 128) {
        const float invN = 1.0f / N_NODES;
        float s = stats[tid], sq = stats[128 + tid];
        float mu = s * invN;
        float var = fmaxf(sq * invN - mu * mu, 0.f);
        float rstd = rsqrtf(var + 1e-5f);
        float sc = rstd * gamma[tid];
        s_sc[tid] = sc;
        s_sh[tid] = beta[tid] - mu * sc;
    }
    __syncthreads();
    int i = blockIdx.x * blockDim.x + tid;
    int stride = gridDim.x * blockDim.x;
    for (; i < n4; i += stride) {
        int j4 = i & 31;
        float4 zv = z[i];
        float4 hv = hin[i];
        float4 sc = ((const float4*)s_sc)[j4];
        float4 sh = ((const float4*)s_sh)[j4];
        float4 o;
        o.x = hv.x + zv.x * sc.x + sh.x;
        o.y = hv.y + zv.y * sc.y + sh.y;
        o.z = hv.z + zv.z * sc.z + sh.z;
        o.w = hv.w + zv.w * sc.w + sh.w;
        hout[i] = o;
    }
}

// ---------------- context attention pooling -> qin[b][0:128] ----------------
__global__ void attn_kernel(const int* __restrict__ ctx_ids, const float* __restrict__ emb,
                            const float* __restrict__ attn_w, const float* __restrict__ attn_b,
                            float* __restrict__ qin) {
    __shared__ float s_ctx[CTX_LEN * D];
    __shared__ float s_aw[D];
    __shared__ float s_logit[64];
    __shared__ float s_wt[64];
    int b = blockIdx.x;
    int tid = threadIdx.x;          // 128 threads
    int lane = tid & 31, wid = tid >> 5;
    s_aw[tid] = attn_w[tid];
    for (int i = tid; i < CTX_LEN * D; i += 128) {
        int l = i >> 7, d = i & 127;
        int id = ctx_ids[b * CTX_LEN + l];
        s_ctx[i] = emb[(size_t)id * D + d];
    }
    __syncthreads();
    for (int l = wid; l < CTX_LEN; l += 4) {
        float p = 0.f;
#pragma unroll
        for (int c = 0; c < 4; c++)
            p += s_ctx[l * D + lane + 32 * c] * s_aw[lane + 32 * c];
#pragma unroll
        for (int off = 16; off; off >>= 1) p += __shfl_xor_sync(0xffffffffu, p, off);
        if (lane == 0) s_logit[l] = p + attn_b[0];
    }
    __syncthreads();
    if (wid == 0) {
        float x0 = (lane < CTX_LEN) ? s_logit[lane] : -1e30f;
        float x1 = (lane + 32 < CTX_LEN) ? s_logit[lane + 32] : -1e30f;
        float m = fmaxf(x0, x1);
#pragma unroll
        for (int off = 16; off; off >>= 1) m = fmaxf(m, __shfl_xor_sync(0xffffffffu, m, off));
        float e0 = (lane < CTX_LEN) ? expf(x0 - m) : 0.f;
        float e1 = (lane + 32 < CTX_LEN) ? expf(x1 - m) : 0.f;
        float s = e0 + e1;
#pragma unroll
        for (int off = 16; off; off >>= 1) s += __shfl_xor_sync(0xffffffffu, s, off);
        float inv = 1.f / s;
        if (lane < CTX_LEN) s_wt[lane] = e0 * inv;
        if (lane + 32 < CTX_LEN) s_wt[lane + 32] = e1 * inv;
    }
    __syncthreads();
    float acc = 0.f;
    for (int l = 0; l < CTX_LEN; l++) acc += s_wt[l] * s_ctx[l * D + tid];
    qin[b * 256 + tid] = acc;
}

// ---------------- launch ----------------
extern "C" void kernel_launch(void* const* d_in, const int* in_sizes, int n_in,
                              void* d_out, int out_size) {
    const int*   edge_index = (const int*)d_in[0];
    const float* norm       = (const float*)d_in[1];
    const int*   ctx_ids    = (const int*)d_in[2];
    const int*   miss_ids   = (const int*)d_in[3];
    const int*   v2fg       = (const int*)d_in[4];
    const float* emb_table  = (const float*)d_in[5];
    const float* fg_emb     = (const float*)d_in[6];
    const float* gc_w       = (const float*)d_in[7];
    const float* bn_gamma   = (const float*)d_in[8];
    const float* bn_beta    = (const float*)d_in[9];
    const float* attn_w     = (const float*)d_in[10];
    const float* attn_b     = (const float*)d_in[11];
    const float* fusion_w   = (const float*)d_in[12];
    const float* fusion_b   = (const float*)d_in[13];
    const float* proj1_w    = (const float*)d_in[14];
    const float* proj1_b    = (const float*)d_in[15];
    const float* proj2_w    = (const float*)d_in[16];
    const float* proj2_b    = (const float*)d_in[17];

    float* out   = (float*)d_out;
    float* query = out;                       // [1024,128]
    float* graph = out + (size_t)BATCH * D;   // [50000,128]

    float *agg, *z, *h, *qin, *q1, *stats;
    int *deg, *offs, *cursor;
    int2 *ep;
    cudaGetSymbolAddress((void**)&agg,    g_agg);
    cudaGetSymbolAddress((void**)&z,      g_z);
    cudaGetSymbolAddress((void**)&h,      g_h);
    cudaGetSymbolAddress((void**)&qin,    g_qin);
    cudaGetSymbolAddress((void**)&q1,     g_q1);
    cudaGetSymbolAddress((void**)&stats,  g_stats);
    cudaGetSymbolAddress((void**)&deg,    g_deg);
    cudaGetSymbolAddress((void**)&offs,   g_offs);
    cudaGetSymbolAddress((void**)&cursor, g_cursor);
    cudaGetSymbolAddress((void**)&ep,     g_epack);

    cudaFuncSetAttribute(gemm_kernel, cudaFuncAttributeMaxDynamicSharedMemorySize, GEMM_SMEM);
    cudaFuncSetAttribute(fusion_gemm_kernel, cudaFuncAttributeMaxDynamicSharedMemorySize, GEMM_SMEM);
    cudaFuncSetAttribute(gcn_gemm_tf32, cudaFuncAttributeMaxDynamicSharedMemorySize, TF_SMEM);

    const int* rows = edge_index;
    const int* cols = edge_index + N_EDGES;
    const int total4 = N_NODES * (D / 4);     // 1.6M float4

    // batch-side attention first (independent of graph path)
    attn_kernel<<<BATCH, 128>>>(ctx_ids, emb_table, attn_w, attn_b, qin);

    // CSR build (once per call; shared by both layers)
    cudaMemsetAsync(deg, 0, N_NODES * sizeof(int), 0);
    hist_kernel<<<3125, 256>>>(rows, deg, stats);
    scan_kernel<<<1, 1024>>>((const int4*)deg, offs, cursor);
    permute_kernel<<<3125, 256>>>(rows, cols, norm, cursor, ep);

    // GCN layers
    for (int l = 0; l < 2; l++) {
        const float* hin = (l == 0) ? fg_emb : h;
        float* lstats = stats + l * 256;
        gather_kernel<<<6250, 256>>>(offs, ep, hin, agg);
        gcn_gemm_tf32<<<782, 256, TF_SMEM>>>(agg, gc_w + (size_t)l * D * D, z, lstats, N_NODES);
        float* hout = (l == 0) ? h : graph;
        bn_res_kernel<<<6250, 256>>>((const float4*)hin, (const float4*)z, lstats,
                                     bn_gamma + l * D, bn_beta + l * D,
                                     (float4*)hout, total4);
    }

    // fusion + projection MLP (miss gather fused into the fusion GEMM A-load)
    fusion_gemm_kernel<<<16, 256, GEMM_SMEM>>>(miss_ids, v2fg, emb_table, graph,
                                               fusion_w, fusion_b, qin + 128);
    gemm_kernel<<<dim3(16, 2), 256, GEMM_SMEM>>>(qin, proj1_w, proj1_b, q1,
                                                 BATCH, 256, 256, 256, 1);
    gemm_kernel<<<dim3(16, 1), 256, GEMM_SMEM>>>(q1, proj2_w, proj2_b, query,
                                                 BATCH, 128, 256, 128, 0);
}

// round 16
// speedup vs baseline: 1.2097x; 1.0729x over previous
#include <cuda_runtime.h>
#include <cstdint>

#define N_NODES 50000
#define N_EDGES 800000
#define D 128
#define VOCAB 30000
#define BATCH 1024
#define CTX_LEN 50

// ---------------- scratch (no allocations allowed) ----------------
__device__ float g_agg[(size_t)N_NODES * D];
__device__ float g_z[(size_t)N_NODES * D];
__device__ float g_h[(size_t)N_NODES * D];
__device__ float g_qin[BATCH * 256];
__device__ float g_stats[512];           // 2 layers x (sum[128], sumsq[128])
__device__ int   g_deg[N_NODES];
__device__ int   g_offs[N_NODES + 4];
__device__ int   g_cursor[N_NODES];
__device__ int2  g_epack[N_EDGES];       // {col, bitcast(norm)}

// ---------------- histogram of edge rows (+ zero BOTH BN stats banks) ----------------
__global__ void hist_kernel(const int* __restrict__ rows, int* __restrict__ deg,
                            float* __restrict__ stats) {
    int e = blockIdx.x * blockDim.x + threadIdx.x;
    if (blockIdx.x == 0 && threadIdx.x < 256) {      // blockDim.x == 256: zero all 512
        stats[threadIdx.x] = 0.f;
        stats[threadIdx.x + 256] = 0.f;
    }
    if (e < N_EDGES) atomicAdd(&deg[rows[e]], 1);
}

// ---------------- exclusive scan of deg -> offs, cursor (single block, int4) --------
__device__ __forceinline__ int warp_incl_scan(int v, int lane) {
#pragma unroll
    for (int o = 1; o < 32; o <<= 1) {
        int t = __shfl_up_sync(0xffffffffu, v, o);
        if (lane >= o) v += t;
    }
    return v;
}

#define N4 (N_NODES / 4)                 // 12500 int4 groups (N_NODES % 4 == 0)

__global__ void scan_kernel(const int4* __restrict__ deg4, int* __restrict__ offs,
                            int* __restrict__ cursor) {
    __shared__ int s_w[32];
    __shared__ int s_ws[32];
    __shared__ int s_carry;
    int tid = threadIdx.x;               // 1024 threads; 4 elems/thread/iter
    int lane = tid & 31, wid = tid >> 5;
    if (tid == 0) s_carry = 0;
    __syncthreads();
    for (int base = 0; base < N4; base += 1024) {
        int i4 = base + tid;
        int4 v = make_int4(0, 0, 0, 0);
        if (i4 < N4) v = deg4[i4];
        int tsum = v.x + v.y + v.z + v.w;
        int ws = warp_incl_scan(tsum, lane);
        if (lane == 31) s_w[wid] = ws;
        __syncthreads();
        if (wid == 0) s_ws[lane] = warp_incl_scan(s_w[lane], lane);
        __syncthreads();
        int excl = s_carry + ws - tsum + (wid ? s_ws[wid - 1] : 0);
        if (i4 < N4) {
            int o0 = excl;
            int o1 = o0 + v.x;
            int o2 = o1 + v.y;
            int o3 = o2 + v.z;
            int i = i4 * 4;
            offs[i] = o0; offs[i + 1] = o1; offs[i + 2] = o2; offs[i + 3] = o3;
            cursor[i] = o0; cursor[i + 1] = o1; cursor[i + 2] = o2; cursor[i + 3] = o3;
        }
        __syncthreads();
        if (tid == 0) s_carry += s_ws[31];
        __syncthreads();
    }
    if (tid == 0) offs[N_NODES] = s_carry;   // == N_EDGES
}

// ---------------- counting-sort permute: packed (col, norm) grouped by row ----------
__global__ void permute_kernel(const int* __restrict__ rows, const int* __restrict__ cols,
                               const float* __restrict__ norm, int* __restrict__ cursor,
                               int2* __restrict__ ep) {
    int e = blockIdx.x * blockDim.x + threadIdx.x;
    if (e >= N_EDGES) return;
    int r = rows[e];
    int pos = atomicAdd(&cursor[r], 1);
    ep[pos] = make_int2(cols[e], __float_as_int(norm[e]));
}

// ---------------- CSR gather: agg[i] = sum_e norm_e * h[col_e]  (no atomics) ----------
__global__ void gather_kernel(const int* __restrict__ offs, const int2* __restrict__ ep,
                              const float* __restrict__ h, float* __restrict__ agg) {
    int warp = blockIdx.x * (blockDim.x >> 5) + (threadIdx.x >> 5);
    if (warp >= N_NODES) return;
    int lane = threadIdx.x & 31;
    int e = offs[warp], end = offs[warp + 1];
    float4 a0 = make_float4(0.f, 0.f, 0.f, 0.f);
    float4 a1 = make_float4(0.f, 0.f, 0.f, 0.f);
    float4 a2 = make_float4(0.f, 0.f, 0.f, 0.f);
    float4 a3 = make_float4(0.f, 0.f, 0.f, 0.f);
    for (; e + 3 < end; e += 4) {
        int2 p0 = ep[e],     p1 = ep[e + 1];
        int2 p2 = ep[e + 2], p3 = ep[e + 3];
        float w0 = __int_as_float(p0.y), w1 = __int_as_float(p1.y);
        float w2 = __int_as_float(p2.y), w3 = __int_as_float(p3.y);
        float4 v0 = *((const float4*)(h + (size_t)p0.x * D) + lane);
        float4 v1 = *((const float4*)(h + (size_t)p1.x * D) + lane);
        float4 v2 = *((const float4*)(h + (size_t)p2.x * D) + lane);
        float4 v3 = *((const float4*)(h + (size_t)p3.x * D) + lane);
        a0.x = fmaf(w0, v0.x, a0.x); a0.y = fmaf(w0, v0.y, a0.y);
        a0.z = fmaf(w0, v0.z, a0.z); a0.w = fmaf(w0, v0.w, a0.w);
        a1.x = fmaf(w1, v1.x, a1.x); a1.y = fmaf(w1, v1.y, a1.y);
        a1.z = fmaf(w1, v1.z, a1.z); a1.w = fmaf(w1, v1.w, a1.w);
        a2.x = fmaf(w2, v2.x, a2.x); a2.y = fmaf(w2, v2.y, a2.y);
        a2.z = fmaf(w2, v2.z, a2.z); a2.w = fmaf(w2, v2.w, a2.w);
        a3.x = fmaf(w3, v3.x, a3.x); a3.y = fmaf(w3, v3.y, a3.y);
        a3.z = fmaf(w3, v3.z, a3.z); a3.w = fmaf(w3, v3.w, a3.w);
    }
    for (; e < end; e++) {
        int2 p0 = ep[e];
        float w0 = __int_as_float(p0.y);
        float4 v0 = *((const float4*)(h + (size_t)p0.x * D) + lane);
        a0.x = fmaf(w0, v0.x, a0.x); a0.y = fmaf(w0, v0.y, a0.y);
        a0.z = fmaf(w0, v0.z, a0.z); a0.w = fmaf(w0, v0.w, a0.w);
    }
    a0.x += a1.x; a0.y += a1.y; a0.z += a1.z; a0.w += a1.w;
    a2.x += a3.x; a2.y += a3.y; a2.z += a3.z; a2.w += a3.w;
    a0.x += a2.x; a0.y += a2.y; a0.z += a2.z; a0.w += a2.w;
    *((float4*)(agg + (size_t)warp * D) + lane) = a0;
}

// ========== tf32x3 tensor-core node GEMM: z = relu(A @ W^T), stats += (sum,sumsq) ====
#define SA 132                                   // smem stride: bank-conflict-free frags
#define TF_SMEM ((64 * SA + 128 * SA) * 4)       // 101376 bytes

__device__ __forceinline__ uint32_t f2tf32(float x) {
    uint32_t r;
    asm("cvt.rna.tf32.f32 %0, %1;" : "=r"(r) : "f"(x));
    return r;
}

#define MMA_TF32(c, a0, a1, a2, a3, b0, b1)                                       \
    asm volatile("mma.sync.aligned.m16n8k8.row.col.f32.tf32.tf32.f32 "            \
                 "{%0,%1,%2,%3}, {%4,%5,%6,%7}, {%8,%9}, {%0,%1,%2,%3};"          \
                 : "+f"((c)[0]), "+f"((c)[1]), "+f"((c)[2]), "+f"((c)[3])         \
                 : "r"(a0), "r"(a1), "r"(a2), "r"(a3), "r"(b0), "r"(b1))

__global__ void __launch_bounds__(256, 2)
gcn_gemm_tf32(const float* __restrict__ A, const float* __restrict__ W,
              float* __restrict__ z, float* __restrict__ stats, int M) {
    extern __shared__ float sm[];
    float* sA = sm;               // [64][SA]
    float* sB = sm + 64 * SA;     // [128][SA]
    int tid = threadIdx.x;
    int lane = tid & 31, wid = tid >> 5;
    int bm = blockIdx.x * 64;

    for (int i = tid; i < 64 * 32; i += 256) {
        int r = i >> 5, c4 = i & 31;
        int gr = bm + r;
        float4 v = make_float4(0.f, 0.f, 0.f, 0.f);
        if (gr < M) v = *(const float4*)(A + (size_t)gr * D + c4 * 4);
        *(float4*)(sA + r * SA + c4 * 4) = v;
    }
    for (int i = tid; i < 128 * 32; i += 256) {
        int n = i >> 5, k4 = i & 31;
        *(float4*)(sB + n * SA + k4 * 4) = *(const float4*)(W + (size_t)n * D + k4 * 4);
    }
    __syncthreads();

    int mbase = (wid & 3) * 16;
    int nbase = (wid >> 2) * 64;
    int row = lane >> 2, kc = lane & 3;

    float acc[8][4];
#pragma unroll
    for (int nf = 0; nf < 8; nf++)
#pragma unroll
        for (int c = 0; c < 4; c++) acc[nf][c] = 0.f;

#pragma unroll 1
    for (int ks = 0; ks < 16; ks++) {
        int k0 = ks * 8;
        float af0 = sA[(mbase + row) * SA + k0 + kc];
        float af1 = sA[(mbase + row + 8) * SA + k0 + kc];
        float af2 = sA[(mbase + row) * SA + k0 + kc + 4];
        float af3 = sA[(mbase + row + 8) * SA + k0 + kc + 4];
        uint32_t ah0 = f2tf32(af0), ah1 = f2tf32(af1), ah2 = f2tf32(af2), ah3 = f2tf32(af3);
        uint32_t al0 = f2tf32(af0 - __uint_as_float(ah0));
        uint32_t al1 = f2tf32(af1 - __uint_as_float(ah1));
        uint32_t al2 = f2tf32(af2 - __uint_as_float(ah2));
        uint32_t al3 = f2tf32(af3 - __uint_as_float(ah3));
#pragma unroll
        for (int nf = 0; nf < 8; nf++) {
            int ncol = nbase + nf * 8 + row;
            float bf0 = sB[ncol * SA + k0 + kc];
            float bf1 = sB[ncol * SA + k0 + kc + 4];
            uint32_t bh0 = f2tf32(bf0), bh1 = f2tf32(bf1);
            uint32_t bl0 = f2tf32(bf0 - __uint_as_float(bh0));
            uint32_t bl1 = f2tf32(bf1 - __uint_as_float(bh1));
            MMA_TF32(acc[nf], ah0, ah1, ah2, ah3, bl0, bl1);
            MMA_TF32(acc[nf], al0, al1, al2, al3, bh0, bh1);
            MMA_TF32(acc[nf], ah0, ah1, ah2, ah3, bh0, bh1);
        }
    }
    __syncthreads();

    float* sOut = sm;
#pragma unroll
    for (int nf = 0; nf < 8; nf++) {
        int r0 = mbase + row;
        int c0 = nbase + nf * 8 + 2 * kc;
        sOut[r0 * SA + c0]           = acc[nf][0];
        sOut[r0 * SA + c0 + 1]       = acc[nf][1];
        sOut[(r0 + 8) * SA + c0]     = acc[nf][2];
        sOut[(r0 + 8) * SA + c0 + 1] = acc[nf][3];
    }
    __syncthreads();

    int rg = wid * 8;
    float psum[4] = {0.f, 0.f, 0.f, 0.f}, psq[4] = {0.f, 0.f, 0.f, 0.f};
#pragma unroll
    for (int i = 0; i < 8; i++) {
        int gr = bm + rg + i;
        if (gr < M) {
#pragma unroll
            for (int c = 0; c < 4; c++) {
                float v = fmaxf(sOut[(rg + i) * SA + lane + 32 * c], 0.f);
                z[(size_t)gr * D + lane + 32 * c] = v;
                psum[c] += v;
                psq[c] += v * v;
            }
        }
    }
    __syncthreads();
    float* s_sum = sm;
    float* s_sq = sm + 128;
    if (tid < 128) { s_sum[tid] = 0.f; s_sq[tid] = 0.f; }
    __syncthreads();
#pragma unroll
    for (int c = 0; c < 4; c++) {
        atomicAdd(&s_sum[lane + 32 * c], psum[c]);
        atomicAdd(&s_sq[lane + 32 * c], psq[c]);
    }
    __syncthreads();
    if (tid < 128) {
        atomicAdd(&stats[tid], s_sum[tid]);
        atomicAdd(&stats[128 + tid], s_sq[tid]);
    }
}

// ---------------- BN apply + residual (computes scale/shift from raw stats) ---------
__global__ void bn_res_kernel(const float4* __restrict__ hin, const float4* __restrict__ z,
                              const float* __restrict__ stats, const float* __restrict__ gamma,
                              const float* __restrict__ beta, float4* __restrict__ hout,
                              int n4) {
    __shared__ float s_sc[128];
    __shared__ float s_sh[128];
    int tid = threadIdx.x;
    if (tid < 128) {
        const float invN = 1.0f / N_NODES;
        float s = stats[tid], sq = stats[128 + tid];
        float mu = s * invN;
        float var = fmaxf(sq * invN - mu * mu, 0.f);
        float rstd = rsqrtf(var + 1e-5f);
        float sc = rstd * gamma[tid];
        s_sc[tid] = sc;
        s_sh[tid] = beta[tid] - mu * sc;
    }
    __syncthreads();
    int i = blockIdx.x * blockDim.x + tid;
    int stride = gridDim.x * blockDim.x;
    for (; i < n4; i += stride) {
        int j4 = i & 31;
        float4 zv = z[i];
        float4 hv = hin[i];
        float4 sc = ((const float4*)s_sc)[j4];
        float4 sh = ((const float4*)s_sh)[j4];
        float4 o;
        o.x = hv.x + zv.x * sc.x + sh.x;
        o.y = hv.y + zv.y * sc.y + sh.y;
        o.z = hv.z + zv.z * sc.z + sh.z;
        o.w = hv.w + zv.w * sc.w + sh.w;
        hout[i] = o;
    }
}

// ---------------- context attention pooling -> qin[b][0:128] (float4 loads) ---------
__global__ void attn_kernel(const int* __restrict__ ctx_ids, const float* __restrict__ emb,
                            const float* __restrict__ attn_w, const float* __restrict__ attn_b,
                            float* __restrict__ qin) {
    __shared__ float s_ctx[CTX_LEN * D];
    __shared__ float s_aw[D];
    __shared__ float s_logit[64];
    __shared__ float s_wt[64];
    int b = blockIdx.x;
    int tid = threadIdx.x;          // 128 threads
    int lane = tid & 31, wid = tid >> 5;
    s_aw[tid] = attn_w[tid];
    // warp-per-row float4 ctx load: warp w loads rows w, w+4, ...
    for (int l = wid; l < CTX_LEN; l += 4) {
        int id = ctx_ids[b * CTX_LEN + l];
        float4 v = *((const float4*)(emb + (size_t)id * D) + lane);
        *(float4*)(s_ctx + l * D + lane * 4) = v;
    }
    __syncthreads();
    for (int l = wid; l < CTX_LEN; l += 4) {
        float p = 0.f;
#pragma unroll
        for (int c = 0; c < 4; c++)
            p += s_ctx[l * D + lane + 32 * c] * s_aw[lane + 32 * c];
#pragma unroll
        for (int off = 16; off; off >>= 1) p += __shfl_xor_sync(0xffffffffu, p, off);
        if (lane == 0) s_logit[l] = p + attn_b[0];
    }
    __syncthreads();
    if (wid == 0) {
        float x0 = (lane < CTX_LEN) ? s_logit[lane] : -1e30f;
        float x1 = (lane + 32 < CTX_LEN) ? s_logit[lane + 32] : -1e30f;
        float m = fmaxf(x0, x1);
#pragma unroll
        for (int off = 16; off; off >>= 1) m = fmaxf(m, __shfl_xor_sync(0xffffffffu, m, off));
        float e0 = (lane < CTX_LEN) ? expf(x0 - m) : 0.f;
        float e1 = (lane + 32 < CTX_LEN) ? expf(x1 - m) : 0.f;
        float s = e0 + e1;
#pragma unroll
        for (int off = 16; off; off >>= 1) s += __shfl_xor_sync(0xffffffffu, s, off);
        float inv = 1.f / s;
        if (lane < CTX_LEN) s_wt[lane] = e0 * inv;
        if (lane + 32 < CTX_LEN) s_wt[lane + 32] = e1 * inv;
    }
    __syncthreads();
    float acc = 0.f;
    for (int l = 0; l < CTX_LEN; l++) acc += s_wt[l] * s_ctx[l * D + tid];
    qin[b * 256 + tid] = acc;
}

// ========== fused batch tail: fusion GEMM + proj1(relu) + proj2, all in one kernel ===
// Block = 256 threads, 16 batch rows. Activation tile stays in smem end-to-end.
#define SBK 129
#define BT_QT   (16 * 256)                         // [16][256] fusion input/output
#define BT_Q1   (16 * 256)                         // [16][256] proj1 output
#define BT_W    (128 * SBK)                        // weight tile
#define BT_F    (16 * 128)                         // gathered fusion A-chunk
#define BT_SMEM ((BT_QT + BT_Q1 + BT_W + BT_F) * 4)

__global__ void __launch_bounds__(256, 2)
batch_tail_kernel(const int* __restrict__ miss_ids, const int* __restrict__ v2fg,
                  const float* __restrict__ emb, const float* __restrict__ graph,
                  const float* __restrict__ qin,
                  const float* __restrict__ fw, const float* __restrict__ fb,
                  const float* __restrict__ p1w, const float* __restrict__ p1b,
                  const float* __restrict__ p2w, const float* __restrict__ p2b,
                  float* __restrict__ query) {
    extern __shared__ float sm[];
    float* qt = sm;                       // [16][256]
    float* q1 = sm + BT_QT;               // [16][256]
    float* sW = sm + BT_QT + BT_Q1;       // [128][SBK]
    float* sF = sW + BT_W;                // [16][128]
    int tid = threadIdx.x;
    int lane = tid & 31, wid = tid >> 5;
    int bm = blockIdx.x * 16;
    int rr = wid * 2;                     // warp owns rows rr, rr+1

    // ctx_emb -> qt[:,0:128]
    for (int i = tid; i < 16 * 32; i += 256) {
        int r = i >> 5, c4 = i & 31;
        *(float4*)(qt + r * 256 + c4 * 4) =
            *(const float4*)(qin + (size_t)(bm + r) * 256 + c4 * 4);
    }

    // --- phase 1: fusion GEMM (K=256, gathered A) -> qt[:,128:256] ---
    float fa[2][4];
#pragma unroll
    for (int i = 0; i < 2; i++)
#pragma unroll
        for (int c = 0; c < 4; c++) fa[i][c] = 0.f;
    for (int k0 = 0; k0 < 256; k0 += 128) {
        __syncthreads();
        for (int i = tid; i < 16 * 32; i += 256) {
            int r = i >> 5, c4 = i & 31;
            int mid = miss_ids[bm + r];
            float4 v;
            if (k0 == 0) {
                v = *(const float4*)(emb + (size_t)mid * D + c4 * 4);
            } else {
                int fg = v2fg[mid];
                v = (fg >= 0) ? *(const float4*)(graph + (size_t)fg * D + c4 * 4)
                              : make_float4(0.f, 0.f, 0.f, 0.f);
            }
            *(float4*)(sF + r * 128 + c4 * 4) = v;
        }
        for (int i = tid; i < 128 * 32; i += 256) {
            int n = i >> 5, k4 = i & 31;
            float4 v = *(const float4*)(fw + (size_t)n * 256 + k0 + k4 * 4);
            float* p = sW + n * SBK + k4 * 4;
            p[0] = v.x; p[1] = v.y; p[2] = v.z; p[3] = v.w;
        }
        __syncthreads();
#pragma unroll 4
        for (int k = 0; k < 128; k++) {
            float b0 = sW[(lane)      * SBK + k];
            float b1 = sW[(lane + 32) * SBK + k];
            float b2 = sW[(lane + 64) * SBK + k];
            float b3 = sW[(lane + 96) * SBK + k];
#pragma unroll
            for (int i = 0; i < 2; i++) {
                float a = sF[(rr + i) * 128 + k];
                fa[i][0] = fmaf(a, b0, fa[i][0]);
                fa[i][1] = fmaf(a, b1, fa[i][1]);
                fa[i][2] = fmaf(a, b2, fa[i][2]);
                fa[i][3] = fmaf(a, b3, fa[i][3]);
            }
        }
    }
#pragma unroll
    for (int i = 0; i < 2; i++)
#pragma unroll
        for (int c = 0; c < 4; c++)
            qt[(rr + i) * 256 + 128 + lane + 32 * c] = fa[i][c] + fb[lane + 32 * c];

    // --- phase 2: proj1 (N=256 in two halves, K=256) -> relu -> q1 ---
    for (int nh = 0; nh < 2; nh++) {
        float pa[2][4];
#pragma unroll
        for (int i = 0; i < 2; i++)
#pragma unroll
            for (int c = 0; c < 4; c++) pa[i][c] = 0.f;
        for (int k0 = 0; k0 < 256; k0 += 128) {
            __syncthreads();            // protects qt writes (first iter) / sW reuse
            for (int i = tid; i < 128 * 32; i += 256) {
                int n = i >> 5, k4 = i & 31;
                float4 v = *(const float4*)(p1w + (size_t)(nh * 128 + n) * 256 + k0 + k4 * 4);
                float* p = sW + n * SBK + k4 * 4;
                p[0] = v.x; p[1] = v.y; p[2] = v.z; p[3] = v.w;
            }
            __syncthreads();
#pragma unroll 4
            for (int k = 0; k < 128; k++) {
                float b0 = sW[(lane)      * SBK + k];
                float b1 = sW[(lane + 32) * SBK + k];
                float b2 = sW[(lane + 64) * SBK + k];
                float b3 = sW[(lane + 96) * SBK + k];
#pragma unroll
                for (int i = 0; i < 2; i++) {
                    float a = qt[(rr + i) * 256 + k0 + k];
                    pa[i][0] = fmaf(a, b0, pa[i][0]);
                    pa[i][1] = fmaf(a, b1, pa[i][1]);
                    pa[i][2] = fmaf(a, b2, pa[i][2]);
                    pa[i][3] = fmaf(a, b3, pa[i][3]);
                }
            }
        }
#pragma unroll
        for (int i = 0; i < 2; i++)
#pragma unroll
            for (int c = 0; c < 4; c++)
                q1[(rr + i) * 256 + nh * 128 + lane + 32 * c] =
                    fmaxf(pa[i][c] + p1b[nh * 128 + lane + 32 * c], 0.f);
    }

    // --- phase 3: proj2 (N=128, K=256) -> query ---
    float qa[2][4];
#pragma unroll
    for (int i = 0; i < 2; i++)
#pragma unroll
        for (int c = 0; c < 4; c++) qa[i][c] = 0.f;
    for (int k0 = 0; k0 < 256; k0 += 128) {
        __syncthreads();                // protects q1 writes (first iter) / sW reuse
        for (int i = tid; i < 128 * 32; i += 256) {
            int n = i >> 5, k4 = i & 31;
            float4 v = *(const float4*)(p2w + (size_t)n * 256 + k0 + k4 * 4);
            float* p = sW + n * SBK + k4 * 4;
            p[0] = v.x; p[1] = v.y; p[2] = v.z; p[3] = v.w;
        }
        __syncthreads();
#pragma unroll 4
        for (int k = 0; k < 128; k++) {
            float b0 = sW[(lane)      * SBK + k];
            float b1 = sW[(lane + 32) * SBK + k];
            float b2 = sW[(lane + 64) * SBK + k];
            float b3 = sW[(lane + 96) * SBK + k];
#pragma unroll
            for (int i = 0; i < 2; i++) {
                float a = q1[(rr + i) * 256 + k0 + k];
                qa[i][0] = fmaf(a, b0, qa[i][0]);
                qa[i][1] = fmaf(a, b1, qa[i][1]);
                qa[i][2] = fmaf(a, b2, qa[i][2]);
                qa[i][3] = fmaf(a, b3, qa[i][3]);
            }
        }
    }
#pragma unroll
    for (int i = 0; i < 2; i++)
#pragma unroll
        for (int c = 0; c < 4; c++)
            query[(size_t)(bm + rr + i) * 128 + lane + 32 * c] =
                qa[i][c] + p2b[lane + 32 * c];
}

// ---------------- launch ----------------
extern "C" void kernel_launch(void* const* d_in, const int* in_sizes, int n_in,
                              void* d_out, int out_size) {
    const int*   edge_index = (const int*)d_in[0];
    const float* norm       = (const float*)d_in[1];
    const int*   ctx_ids    = (const int*)d_in[2];
    const int*   miss_ids   = (const int*)d_in[3];
    const int*   v2fg       = (const int*)d_in[4];
    const float* emb_table  = (const float*)d_in[5];
    const float* fg_emb     = (const float*)d_in[6];
    const float* gc_w       = (const float*)d_in[7];
    const float* bn_gamma   = (const float*)d_in[8];
    const float* bn_beta    = (const float*)d_in[9];
    const float* attn_w     = (const float*)d_in[10];
    const float* attn_b     = (const float*)d_in[11];
    const float* fusion_w   = (const float*)d_in[12];
    const float* fusion_b   = (const float*)d_in[13];
    const float* proj1_w    = (const float*)d_in[14];
    const float* proj1_b    = (const float*)d_in[15];
    const float* proj2_w    = (const float*)d_in[16];
    const float* proj2_b    = (const float*)d_in[17];

    float* out   = (float*)d_out;
    float* query = out;                       // [1024,128]
    float* graph = out + (size_t)BATCH * D;   // [50000,128]

    float *agg, *z, *h, *qin, *stats;
    int *deg, *offs, *cursor;
    int2 *ep;
    cudaGetSymbolAddress((void**)&agg,    g_agg);
    cudaGetSymbolAddress((void**)&z,      g_z);
    cudaGetSymbolAddress((void**)&h,      g_h);
    cudaGetSymbolAddress((void**)&qin,    g_qin);
    cudaGetSymbolAddress((void**)&stats,  g_stats);
    cudaGetSymbolAddress((void**)&deg,    g_deg);
    cudaGetSymbolAddress((void**)&offs,   g_offs);
    cudaGetSymbolAddress((void**)&cursor, g_cursor);
    cudaGetSymbolAddress((void**)&ep,     g_epack);

    cudaFuncSetAttribute(gcn_gemm_tf32, cudaFuncAttributeMaxDynamicSharedMemorySize, TF_SMEM);
    cudaFuncSetAttribute(batch_tail_kernel, cudaFuncAttributeMaxDynamicSharedMemorySize, BT_SMEM);

    const int* rows = edge_index;
    const int* cols = edge_index + N_EDGES;
    const int total4 = N_NODES * (D / 4);     // 1.6M float4

    // batch-side attention first (independent of graph path)
    attn_kernel<<<BATCH, 128>>>(ctx_ids, emb_table, attn_w, attn_b, qin);

    // CSR build (once per call; shared by both layers)
    cudaMemsetAsync(deg, 0, N_NODES * sizeof(int), 0);
    hist_kernel<<<3125, 256>>>(rows, deg, stats);
    scan_kernel<<<1, 1024>>>((const int4*)deg, offs, cursor);
    permute_kernel<<<3125, 256>>>(rows, cols, norm, cursor, ep);

    // GCN layers
    for (int l = 0; l < 2; l++) {
        const float* hin = (l == 0) ? fg_emb : h;
        float* lstats = stats + l * 256;
        gather_kernel<<<6250, 256>>>(offs, ep, hin, agg);
        gcn_gemm_tf32<<<782, 256, TF_SMEM>>>(agg, gc_w + (size_t)l * D * D, z, lstats, N_NODES);
        float* hout = (l == 0) ? h : graph;
        bn_res_kernel<<<6250, 256>>>((const float4*)hin, (const float4*)z, lstats,
                                     bn_gamma + l * D, bn_beta + l * D,
                                     (float4*)hout, total4);
    }

    // fused batch tail: fusion + proj1(relu) + proj2 in one launch
    batch_tail_kernel<<<BATCH / 16, 256, BT_SMEM>>>(miss_ids, v2fg, emb_table, graph, qin,
                                                    fusion_w, fusion_b, proj1_w, proj1_b,
                                                    proj2_w, proj2_b, query);
}

// round 17
// speedup vs baseline: 1.2175x; 1.0064x over previous
#include <cuda_runtime.h>
#include <cstdint>

#define N_NODES 50000
#define N_EDGES 800000
#define D 128
#define VOCAB 30000
#define BATCH 1024
#define CTX_LEN 50

// ---------------- scratch (no allocations allowed) ----------------
__device__ float g_agg[(size_t)N_NODES * D];
__device__ float g_z[(size_t)N_NODES * D];
__device__ float g_h[(size_t)N_NODES * D];
__device__ float g_qin[BATCH * 256];
__device__ float g_stats[512];           // 2 layers x (sum[128], sumsq[128])
__device__ int   g_deg[N_NODES];
__device__ int   g_offs[N_NODES + 4];
__device__ int   g_cursor[N_NODES];
__device__ int2  g_epack[N_EDGES];       // {col, bitcast(norm)}

#define E4 (N_EDGES / 4)                 // 200000 (N_EDGES % 4 == 0)

// ---------------- histogram of edge rows, 4 edges/thread (+ zero BN stats) ----------
__global__ void hist_kernel(const int4* __restrict__ rows4, int* __restrict__ deg,
                            float* __restrict__ stats) {
    int i = blockIdx.x * blockDim.x + threadIdx.x;
    if (blockIdx.x == 0 && threadIdx.x < 256) {      // blockDim.x == 256: zero all 512
        stats[threadIdx.x] = 0.f;
        stats[threadIdx.x + 256] = 0.f;
    }
    if (i < E4) {
        int4 r = rows4[i];
        atomicAdd(&deg[r.x], 1);
        atomicAdd(&deg[r.y], 1);
        atomicAdd(&deg[r.z], 1);
        atomicAdd(&deg[r.w], 1);
    }
}

// ---------------- exclusive scan of deg -> offs, cursor (single block, int4) --------
__device__ __forceinline__ int warp_incl_scan(int v, int lane) {
#pragma unroll
    for (int o = 1; o < 32; o <<= 1) {
        int t = __shfl_up_sync(0xffffffffu, v, o);
        if (lane >= o) v += t;
    }
    return v;
}

#define N4 (N_NODES / 4)                 // 12500 int4 groups (N_NODES % 4 == 0)

__global__ void scan_kernel(const int4* __restrict__ deg4, int* __restrict__ offs,
                            int* __restrict__ cursor) {
    __shared__ int s_w[32];
    __shared__ int s_ws[32];
    __shared__ int s_carry;
    int tid = threadIdx.x;               // 1024 threads; 4 elems/thread/iter
    int lane = tid & 31, wid = tid >> 5;
    if (tid == 0) s_carry = 0;
    __syncthreads();
    for (int base = 0; base < N4; base += 1024) {
        int i4 = base + tid;
        int4 v = make_int4(0, 0, 0, 0);
        if (i4 < N4) v = deg4[i4];
        int tsum = v.x + v.y + v.z + v.w;
        int ws = warp_incl_scan(tsum, lane);
        if (lane == 31) s_w[wid] = ws;
        __syncthreads();
        if (wid == 0) s_ws[lane] = warp_incl_scan(s_w[lane], lane);
        __syncthreads();
        int excl = s_carry + ws - tsum + (wid ? s_ws[wid - 1] : 0);
        if (i4 < N4) {
            int o0 = excl;
            int o1 = o0 + v.x;
            int o2 = o1 + v.y;
            int o3 = o2 + v.z;
            int i = i4 * 4;
            offs[i] = o0; offs[i + 1] = o1; offs[i + 2] = o2; offs[i + 3] = o3;
            cursor[i] = o0; cursor[i + 1] = o1; cursor[i + 2] = o2; cursor[i + 3] = o3;
        }
        __syncthreads();
        if (tid == 0) s_carry += s_ws[31];
        __syncthreads();
    }
    if (tid == 0) offs[N_NODES] = s_carry;   // == N_EDGES
}

// -------- counting-sort permute, 4 edges/thread: packed (col, norm) grouped by row --
__global__ void permute_kernel(const int4* __restrict__ rows4, const int4* __restrict__ cols4,
                               const float4* __restrict__ norm4, int* __restrict__ cursor,
                               int2* __restrict__ ep) {
    int i = blockIdx.x * blockDim.x + threadIdx.x;
    if (i >= E4) return;
    int4 r = rows4[i];
    int4 c = cols4[i];
    float4 w = norm4[i];
    int p0 = atomicAdd(&cursor[r.x], 1);
    int p1 = atomicAdd(&cursor[r.y], 1);
    int p2 = atomicAdd(&cursor[r.z], 1);
    int p3 = atomicAdd(&cursor[r.w], 1);
    ep[p0] = make_int2(c.x, __float_as_int(w.x));
    ep[p1] = make_int2(c.y, __float_as_int(w.y));
    ep[p2] = make_int2(c.z, __float_as_int(w.z));
    ep[p3] = make_int2(c.w, __float_as_int(w.w));
}

// ---------------- CSR gather: agg[i] = sum_e norm_e * h[col_e]  (no atomics) ----------
__global__ void gather_kernel(const int* __restrict__ offs, const int2* __restrict__ ep,
                              const float* __restrict__ h, float* __restrict__ agg) {
    int warp = blockIdx.x * (blockDim.x >> 5) + (threadIdx.x >> 5);
    if (warp >= N_NODES) return;
    int lane = threadIdx.x & 31;
    int e = offs[warp], end = offs[warp + 1];
    float4 a0 = make_float4(0.f, 0.f, 0.f, 0.f);
    float4 a1 = make_float4(0.f, 0.f, 0.f, 0.f);
    float4 a2 = make_float4(0.f, 0.f, 0.f, 0.f);
    float4 a3 = make_float4(0.f, 0.f, 0.f, 0.f);
    for (; e + 3 < end; e += 4) {
        int2 p0 = ep[e],     p1 = ep[e + 1];
        int2 p2 = ep[e + 2], p3 = ep[e + 3];
        float w0 = __int_as_float(p0.y), w1 = __int_as_float(p1.y);
        float w2 = __int_as_float(p2.y), w3 = __int_as_float(p3.y);
        float4 v0 = *((const float4*)(h + (size_t)p0.x * D) + lane);
        float4 v1 = *((const float4*)(h + (size_t)p1.x * D) + lane);
        float4 v2 = *((const float4*)(h + (size_t)p2.x * D) + lane);
        float4 v3 = *((const float4*)(h + (size_t)p3.x * D) + lane);
        a0.x = fmaf(w0, v0.x, a0.x); a0.y = fmaf(w0, v0.y, a0.y);
        a0.z = fmaf(w0, v0.z, a0.z); a0.w = fmaf(w0, v0.w, a0.w);
        a1.x = fmaf(w1, v1.x, a1.x); a1.y = fmaf(w1, v1.y, a1.y);
        a1.z = fmaf(w1, v1.z, a1.z); a1.w = fmaf(w1, v1.w, a1.w);
        a2.x = fmaf(w2, v2.x, a2.x); a2.y = fmaf(w2, v2.y, a2.y);
        a2.z = fmaf(w2, v2.z, a2.z); a2.w = fmaf(w2, v2.w, a2.w);
        a3.x = fmaf(w3, v3.x, a3.x); a3.y = fmaf(w3, v3.y, a3.y);
        a3.z = fmaf(w3, v3.z, a3.z); a3.w = fmaf(w3, v3.w, a3.w);
    }
    for (; e < end; e++) {
        int2 p0 = ep[e];
        float w0 = __int_as_float(p0.y);
        float4 v0 = *((const float4*)(h + (size_t)p0.x * D) + lane);
        a0.x = fmaf(w0, v0.x, a0.x); a0.y = fmaf(w0, v0.y, a0.y);
        a0.z = fmaf(w0, v0.z, a0.z); a0.w = fmaf(w0, v0.w, a0.w);
    }
    a0.x += a1.x; a0.y += a1.y; a0.z += a1.z; a0.w += a1.w;
    a2.x += a3.x; a2.y += a3.y; a2.z += a3.z; a2.w += a3.w;
    a0.x += a2.x; a0.y += a2.y; a0.z += a2.z; a0.w += a2.w;
    *((float4*)(agg + (size_t)warp * D) + lane) = a0;
}

// ========== tf32x3 tensor-core node GEMM: z = relu(A @ W^T), stats += (sum,sumsq) ====
#define SA 132                                   // smem stride: bank-conflict-free frags
#define TF_SMEM ((64 * SA + 128 * SA) * 4)       // 101376 bytes

__device__ __forceinline__ uint32_t f2tf32(float x) {
    uint32_t r;
    asm("cvt.rna.tf32.f32 %0, %1;" : "=r"(r) : "f"(x));
    return r;
}

#define MMA_TF32(c, a0, a1, a2, a3, b0, b1)                                       \
    asm volatile("mma.sync.aligned.m16n8k8.row.col.f32.tf32.tf32.f32 "            \
                 "{%0,%1,%2,%3}, {%4,%5,%6,%7}, {%8,%9}, {%0,%1,%2,%3};"          \
                 : "+f"((c)[0]), "+f"((c)[1]), "+f"((c)[2]), "+f"((c)[3])         \
                 : "r"(a0), "r"(a1), "r"(a2), "r"(a3), "r"(b0), "r"(b1))

__global__ void __launch_bounds__(256, 2)
gcn_gemm_tf32(const float* __restrict__ A, const float* __restrict__ W,
              float* __restrict__ z, float* __restrict__ stats, int M) {
    extern __shared__ float sm[];
    float* sA = sm;               // [64][SA]
    float* sB = sm + 64 * SA;     // [128][SA]
    int tid = threadIdx.x;
    int lane = tid & 31, wid = tid >> 5;
    int bm = blockIdx.x * 64;

    for (int i = tid; i < 64 * 32; i += 256) {
        int r = i >> 5, c4 = i & 31;
        int gr = bm + r;
        float4 v = make_float4(0.f, 0.f, 0.f, 0.f);
        if (gr < M) v = *(const float4*)(A + (size_t)gr * D + c4 * 4);
        *(float4*)(sA + r * SA + c4 * 4) = v;
    }
    for (int i = tid; i < 128 * 32; i += 256) {
        int n = i >> 5, k4 = i & 31;
        *(float4*)(sB + n * SA + k4 * 4) = *(const float4*)(W + (size_t)n * D + k4 * 4);
    }
    __syncthreads();

    int mbase = (wid & 3) * 16;
    int nbase = (wid >> 2) * 64;
    int row = lane >> 2, kc = lane & 3;

    float acc[8][4];
#pragma unroll
    for (int nf = 0; nf < 8; nf++)
#pragma unroll
        for (int c = 0; c < 4; c++) acc[nf][c] = 0.f;

#pragma unroll 1
    for (int ks = 0; ks < 16; ks++) {
        int k0 = ks * 8;
        float af0 = sA[(mbase + row) * SA + k0 + kc];
        float af1 = sA[(mbase + row + 8) * SA + k0 + kc];
        float af2 = sA[(mbase + row) * SA + k0 + kc + 4];
        float af3 = sA[(mbase + row + 8) * SA + k0 + kc + 4];
        uint32_t ah0 = f2tf32(af0), ah1 = f2tf32(af1), ah2 = f2tf32(af2), ah3 = f2tf32(af3);
        uint32_t al0 = f2tf32(af0 - __uint_as_float(ah0));
        uint32_t al1 = f2tf32(af1 - __uint_as_float(ah1));
        uint32_t al2 = f2tf32(af2 - __uint_as_float(ah2));
        uint32_t al3 = f2tf32(af3 - __uint_as_float(ah3));
#pragma unroll
        for (int nf = 0; nf < 8; nf++) {
            int ncol = nbase + nf * 8 + row;
            float bf0 = sB[ncol * SA + k0 + kc];
            float bf1 = sB[ncol * SA + k0 + kc + 4];
            uint32_t bh0 = f2tf32(bf0), bh1 = f2tf32(bf1);
            uint32_t bl0 = f2tf32(bf0 - __uint_as_float(bh0));
            uint32_t bl1 = f2tf32(bf1 - __uint_as_float(bh1));
            MMA_TF32(acc[nf], ah0, ah1, ah2, ah3, bl0, bl1);
            MMA_TF32(acc[nf], al0, al1, al2, al3, bh0, bh1);
            MMA_TF32(acc[nf], ah0, ah1, ah2, ah3, bh0, bh1);
        }
    }
    __syncthreads();

    float* sOut = sm;
#pragma unroll
    for (int nf = 0; nf < 8; nf++) {
        int r0 = mbase + row;
        int c0 = nbase + nf * 8 + 2 * kc;
        sOut[r0 * SA + c0]           = acc[nf][0];
        sOut[r0 * SA + c0 + 1]       = acc[nf][1];
        sOut[(r0 + 8) * SA + c0]     = acc[nf][2];
        sOut[(r0 + 8) * SA + c0 + 1] = acc[nf][3];
    }
    __syncthreads();

    int rg = wid * 8;
    float psum[4] = {0.f, 0.f, 0.f, 0.f}, psq[4] = {0.f, 0.f, 0.f, 0.f};
#pragma unroll
    for (int i = 0; i < 8; i++) {
        int gr = bm + rg + i;
        if (gr < M) {
#pragma unroll
            for (int c = 0; c < 4; c++) {
                float v = fmaxf(sOut[(rg + i) * SA + lane + 32 * c], 0.f);
                z[(size_t)gr * D + lane + 32 * c] = v;
                psum[c] += v;
                psq[c] += v * v;
            }
        }
    }
    __syncthreads();
    float* s_sum = sm;
    float* s_sq = sm + 128;
    if (tid < 128) { s_sum[tid] = 0.f; s_sq[tid] = 0.f; }
    __syncthreads();
#pragma unroll
    for (int c = 0; c < 4; c++) {
        atomicAdd(&s_sum[lane + 32 * c], psum[c]);
        atomicAdd(&s_sq[lane + 32 * c], psq[c]);
    }
    __syncthreads();
    if (tid < 128) {
        atomicAdd(&stats[tid], s_sum[tid]);
        atomicAdd(&stats[128 + tid], s_sq[tid]);
    }
}

// ---------------- BN apply + residual (computes scale/shift from raw stats) ---------
__global__ void bn_res_kernel(const float4* __restrict__ hin, const float4* __restrict__ z,
                              const float* __restrict__ stats, const float* __restrict__ gamma,
                              const float* __restrict__ beta, float4* __restrict__ hout,
                              int n4) {
    __shared__ float s_sc[128];
    __shared__ float s_sh[128];
    int tid = threadIdx.x;
    if (tid < 128) {
        const float invN = 1.0f / N_NODES;
        float s = stats[tid], sq = stats[128 + tid];
        float mu = s * invN;
        float var = fmaxf(sq * invN - mu * mu, 0.f);
        float rstd = rsqrtf(var + 1e-5f);
        float sc = rstd * gamma[tid];
        s_sc[tid] = sc;
        s_sh[tid] = beta[tid] - mu * sc;
    }
    __syncthreads();
    int i = blockIdx.x * blockDim.x + tid;
    int stride = gridDim.x * blockDim.x;
    for (; i < n4; i += stride) {
        int j4 = i & 31;
        float4 zv = z[i];
        float4 hv = hin[i];
        float4 sc = ((const float4*)s_sc)[j4];
        float4 sh = ((const float4*)s_sh)[j4];
        float4 o;
        o.x = hv.x + zv.x * sc.x + sh.x;
        o.y = hv.y + zv.y * sc.y + sh.y;
        o.z = hv.z + zv.z * sc.z + sh.z;
        o.w = hv.w + zv.w * sc.w + sh.w;
        hout[i] = o;
    }
}

// ------- context attention pooling -> qin[b][0:128] (float4 loads; + zero deg) -------
__global__ void attn_kernel(const int* __restrict__ ctx_ids, const float* __restrict__ emb,
                            const float* __restrict__ attn_w, const float* __restrict__ attn_b,
                            float* __restrict__ qin, int* __restrict__ deg) {
    __shared__ float s_ctx[CTX_LEN * D];
    __shared__ float s_aw[D];
    __shared__ float s_logit[64];
    __shared__ float s_wt[64];
    int b = blockIdx.x;
    int tid = threadIdx.x;          // 128 threads
    int lane = tid & 31, wid = tid >> 5;
    // fold deg zeroing into this kernel (runs before hist in stream order)
    for (int i = b * 128 + tid; i < N_NODES; i += BATCH * 128) deg[i] = 0;
    s_aw[tid] = attn_w[tid];
    // warp-per-row float4 ctx load: warp w loads rows w, w+4, ...
    for (int l = wid; l < CTX_LEN; l += 4) {
        int id = ctx_ids[b * CTX_LEN + l];
        float4 v = *((const float4*)(emb + (size_t)id * D) + lane);
        *(float4*)(s_ctx + l * D + lane * 4) = v;
    }
    __syncthreads();
    for (int l = wid; l < CTX_LEN; l += 4) {
        float p = 0.f;
#pragma unroll
        for (int c = 0; c < 4; c++)
            p += s_ctx[l * D + lane + 32 * c] * s_aw[lane + 32 * c];
#pragma unroll
        for (int off = 16; off; off >>= 1) p += __shfl_xor_sync(0xffffffffu, p, off);
        if (lane == 0) s_logit[l] = p + attn_b[0];
    }
    __syncthreads();
    if (wid == 0) {
        float x0 = (lane < CTX_LEN) ? s_logit[lane] : -1e30f;
        float x1 = (lane + 32 < CTX_LEN) ? s_logit[lane + 32] : -1e30f;
        float m = fmaxf(x0, x1);
#pragma unroll
        for (int off = 16; off; off >>= 1) m = fmaxf(m, __shfl_xor_sync(0xffffffffu, m, off));
        float e0 = (lane < CTX_LEN) ? expf(x0 - m) : 0.f;
        float e1 = (lane + 32 < CTX_LEN) ? expf(x1 - m) : 0.f;
        float s = e0 + e1;
#pragma unroll
        for (int off = 16; off; off >>= 1) s += __shfl_xor_sync(0xffffffffu, s, off);
        float inv = 1.f / s;
        if (lane < CTX_LEN) s_wt[lane] = e0 * inv;
        if (lane + 32 < CTX_LEN) s_wt[lane + 32] = e1 * inv;
    }
    __syncthreads();
    float acc = 0.f;
    for (int l = 0; l < CTX_LEN; l++) acc += s_wt[l] * s_ctx[l * D + tid];
    qin[b * 256 + tid] = acc;
}

// ========== fused batch tail: fusion GEMM + proj1(relu) + proj2, all in one kernel ===
// Block = 256 threads, 16 batch rows. Activation tile stays in smem end-to-end.
#define SBK 129
#define BT_QT   (16 * 256)                         // [16][256] fusion input/output
#define BT_Q1   (16 * 256)                         // [16][256] proj1 output
#define BT_W    (128 * SBK)                        // weight tile
#define BT_F    (16 * 128)                         // gathered fusion A-chunk
#define BT_SMEM ((BT_QT + BT_Q1 + BT_W + BT_F) * 4)

__global__ void __launch_bounds__(256, 2)
batch_tail_kernel(const int* __restrict__ miss_ids, const int* __restrict__ v2fg,
                  const float* __restrict__ emb, const float* __restrict__ graph,
                  const float* __restrict__ qin,
                  const float* __restrict__ fw, const float* __restrict__ fb,
                  const float* __restrict__ p1w, const float* __restrict__ p1b,
                  const float* __restrict__ p2w, const float* __restrict__ p2b,
                  float* __restrict__ query) {
    extern __shared__ float sm[];
    float* qt = sm;                       // [16][256]
    float* q1 = sm + BT_QT;               // [16][256]
    float* sW = sm + BT_QT + BT_Q1;       // [128][SBK]
    float* sF = sW + BT_W;                // [16][128]
    int tid = threadIdx.x;
    int lane = tid & 31, wid = tid >> 5;
    int bm = blockIdx.x * 16;
    int rr = wid * 2;                     // warp owns rows rr, rr+1

    // ctx_emb -> qt[:,0:128]
    for (int i = tid; i < 16 * 32; i += 256) {
        int r = i >> 5, c4 = i & 31;
        *(float4*)(qt + r * 256 + c4 * 4) =
            *(const float4*)(qin + (size_t)(bm + r) * 256 + c4 * 4);
    }

    // --- phase 1: fusion GEMM (K=256, gathered A) -> qt[:,128:256] ---
    float fa[2][4];
#pragma unroll
    for (int i = 0; i < 2; i++)
#pragma unroll
        for (int c = 0; c < 4; c++) fa[i][c] = 0.f;
    for (int k0 = 0; k0 < 256; k0 += 128) {
        __syncthreads();
        for (int i = tid; i < 16 * 32; i += 256) {
            int r = i >> 5, c4 = i & 31;
            int mid = miss_ids[bm + r];
            float4 v;
            if (k0 == 0) {
                v = *(const float4*)(emb + (size_t)mid * D + c4 * 4);
            } else {
                int fg = v2fg[mid];
                v = (fg >= 0) ? *(const float4*)(graph + (size_t)fg * D + c4 * 4)
                              : make_float4(0.f, 0.f, 0.f, 0.f);
            }
            *(float4*)(sF + r * 128 + c4 * 4) = v;
        }
        for (int i = tid; i < 128 * 32; i += 256) {
            int n = i >> 5, k4 = i & 31;
            float4 v = *(const float4*)(fw + (size_t)n * 256 + k0 + k4 * 4);
            float* p = sW + n * SBK + k4 * 4;
            p[0] = v.x; p[1] = v.y; p[2] = v.z; p[3] = v.w;
        }
        __syncthreads();
#pragma unroll 4
        for (int k = 0; k < 128; k++) {
            float b0 = sW[(lane)      * SBK + k];
            float b1 = sW[(lane + 32) * SBK + k];
            float b2 = sW[(lane + 64) * SBK + k];
            float b3 = sW[(lane + 96) * SBK + k];
#pragma unroll
            for (int i = 0; i < 2; i++) {
                float a = sF[(rr + i) * 128 + k];
                fa[i][0] = fmaf(a, b0, fa[i][0]);
                fa[i][1] = fmaf(a, b1, fa[i][1]);
                fa[i][2] = fmaf(a, b2, fa[i][2]);
                fa[i][3] = fmaf(a, b3, fa[i][3]);
            }
        }
    }
#pragma unroll
    for (int i = 0; i < 2; i++)
#pragma unroll
        for (int c = 0; c < 4; c++)
            qt[(rr + i) * 256 + 128 + lane + 32 * c] = fa[i][c] + fb[lane + 32 * c];

    // --- phase 2: proj1 (N=256 in two halves, K=256) -> relu -> q1 ---
    for (int nh = 0; nh < 2; nh++) {
        float pa[2][4];
#pragma unroll
        for (int i = 0; i < 2; i++)
#pragma unroll
            for (int c = 0; c < 4; c++) pa[i][c] = 0.f;
        for (int k0 = 0; k0 < 256; k0 += 128) {
            __syncthreads();            // protects qt writes (first iter) / sW reuse
            for (int i = tid; i < 128 * 32; i += 256) {
                int n = i >> 5, k4 = i & 31;
                float4 v = *(const float4*)(p1w + (size_t)(nh * 128 + n) * 256 + k0 + k4 * 4);
                float* p = sW + n * SBK + k4 * 4;
                p[0] = v.x; p[1] = v.y; p[2] = v.z; p[3] = v.w;
            }
            __syncthreads();
#pragma unroll 4
            for (int k = 0; k < 128; k++) {
                float b0 = sW[(lane)      * SBK + k];
                float b1 = sW[(lane + 32) * SBK + k];
                float b2 = sW[(lane + 64) * SBK + k];
                float b3 = sW[(lane + 96) * SBK + k];
#pragma unroll
                for (int i = 0; i < 2; i++) {
                    float a = qt[(rr + i) * 256 + k0 + k];
                    pa[i][0] = fmaf(a, b0, pa[i][0]);
                    pa[i][1] = fmaf(a, b1, pa[i][1]);
                    pa[i][2] = fmaf(a, b2, pa[i][2]);
                    pa[i][3] = fmaf(a, b3, pa[i][3]);
                }
            }
        }
#pragma unroll
        for (int i = 0; i < 2; i++)
#pragma unroll
            for (int c = 0; c < 4; c++)
                q1[(rr + i) * 256 + nh * 128 + lane + 32 * c] =
                    fmaxf(pa[i][c] + p1b[nh * 128 + lane + 32 * c], 0.f);
    }

    // --- phase 3: proj2 (N=128, K=256) -> query ---
    float qa[2][4];
#pragma unroll
    for (int i = 0; i < 2; i++)
#pragma unroll
        for (int c = 0; c < 4; c++) qa[i][c] = 0.f;
    for (int k0 = 0; k0 < 256; k0 += 128) {
        __syncthreads();                // protects q1 writes (first iter) / sW reuse
        for (int i = tid; i < 128 * 32; i += 256) {
            int n = i >> 5, k4 = i & 31;
            float4 v = *(const float4*)(p2w + (size_t)n * 256 + k0 + k4 * 4);
            float* p = sW + n * SBK + k4 * 4;
            p[0] = v.x; p[1] = v.y; p[2] = v.z; p[3] = v.w;
        }
        __syncthreads();
#pragma unroll 4
        for (int k = 0; k < 128; k++) {
            float b0 = sW[(lane)      * SBK + k];
            float b1 = sW[(lane + 32) * SBK + k];
            float b2 = sW[(lane + 64) * SBK + k];
            float b3 = sW[(lane + 96) * SBK + k];
#pragma unroll
            for (int i = 0; i < 2; i++) {
                float a = q1[(rr + i) * 256 + k0 + k];
                qa[i][0] = fmaf(a, b0, qa[i][0]);
                qa[i][1] = fmaf(a, b1, qa[i][1]);
                qa[i][2] = fmaf(a, b2, qa[i][2]);
                qa[i][3] = fmaf(a, b3, qa[i][3]);
            }
        }
    }
#pragma unroll
    for (int i = 0; i < 2; i++)
#pragma unroll
        for (int c = 0; c < 4; c++)
            query[(size_t)(bm + rr + i) * 128 + lane + 32 * c] =
                qa[i][c] + p2b[lane + 32 * c];
}

// ---------------- launch ----------------
extern "C" void kernel_launch(void* const* d_in, const int* in_sizes, int n_in,
                              void* d_out, int out_size) {
    const int*   edge_index = (const int*)d_in[0];
    const float* norm       = (const float*)d_in[1];
    const int*   ctx_ids    = (const int*)d_in[2];
    const int*   miss_ids   = (const int*)d_in[3];
    const int*   v2fg       = (const int*)d_in[4];
    const float* emb_table  = (const float*)d_in[5];
    const float* fg_emb     = (const float*)d_in[6];
    const float* gc_w       = (const float*)d_in[7];
    const float* bn_gamma   = (const float*)d_in[8];
    const float* bn_beta    = (const float*)d_in[9];
    const float* attn_w     = (const float*)d_in[10];
    const float* attn_b     = (const float*)d_in[11];
    const float* fusion_w   = (const float*)d_in[12];
    const float* fusion_b   = (const float*)d_in[13];
    const float* proj1_w    = (const float*)d_in[14];
    const float* proj1_b    = (const float*)d_in[15];
    const float* proj2_w    = (const float*)d_in[16];
    const float* proj2_b    = (const float*)d_in[17];

    float* out   = (float*)d_out;
    float* query = out;                       // [1024,128]
    float* graph = out + (size_t)BATCH * D;   // [50000,128]

    float *agg, *z, *h, *qin, *stats;
    int *deg, *offs, *cursor;
    int2 *ep;
    cudaGetSymbolAddress((void**)&agg,    g_agg);
    cudaGetSymbolAddress((void**)&z,      g_z);
    cudaGetSymbolAddress((void**)&h,      g_h);
    cudaGetSymbolAddress((void**)&qin,    g_qin);
    cudaGetSymbolAddress((void**)&stats,  g_stats);
    cudaGetSymbolAddress((void**)&deg,    g_deg);
    cudaGetSymbolAddress((void**)&offs,   g_offs);
    cudaGetSymbolAddress((void**)&cursor, g_cursor);
    cudaGetSymbolAddress((void**)&ep,     g_epack);

    cudaFuncSetAttribute(gcn_gemm_tf32, cudaFuncAttributeMaxDynamicSharedMemorySize, TF_SMEM);
    cudaFuncSetAttribute(batch_tail_kernel, cudaFuncAttributeMaxDynamicSharedMemorySize, BT_SMEM);

    const int* rows = edge_index;
    const int* cols = edge_index + N_EDGES;
    const int total4 = N_NODES * (D / 4);     // 1.6M float4

    // batch-side attention first (also zeroes deg; independent of graph path)
    attn_kernel<<<BATCH, 128>>>(ctx_ids, emb_table, attn_w, attn_b, qin, deg);

    // CSR build (once per call; shared by both layers)
    hist_kernel<<<782, 256>>>((const int4*)rows, deg, stats);
    scan_kernel<<<1, 1024>>>((const int4*)deg, offs, cursor);
    permute_kernel<<<782, 256>>>((const int4*)rows, (const int4*)cols,
                                 (const float4*)norm, cursor, ep);

    // GCN layers
    for (int l = 0; l < 2; l++) {
        const float* hin = (l == 0) ? fg_emb : h;
        float* lstats = stats + l * 256;
        gather_kernel<<<6250, 256>>>(offs, ep, hin, agg);
        gcn_gemm_tf32<<<782, 256, TF_SMEM>>>(agg, gc_w + (size_t)l * D * D, z, lstats, N_NODES);
        float* hout = (l == 0) ? h : graph;
        bn_res_kernel<<<6250, 256>>>((const float4*)hin, (const float4*)z, lstats,
                                     bn_gamma + l * D, bn_beta + l * D,
                                     (float4*)hout, total4);
    }

    // fused batch tail: fusion + proj1(relu) + proj2 in one launch
    batch_tail_kernel<<<BATCH / 16, 256, BT_SMEM>>>(miss_ids, v2fg, emb_table, graph, qin,
                                                    fusion_w, fusion_b, proj1_w, proj1_b,
                                                    proj2_w, proj2_b, query);
}